// round 8
// baseline (speedup 1.0000x reference)
#include <cuda_runtime.h>
#include <cuda_bf16.h>
#include <cstdint>

#define T 8
#define V 10000
#define E 100000
#define C_IN 128
#define H 256
#define DS 16
#define C_OUT 64
#define HD (H * DS)          // 4096
#define TV (T * V)           // 80000

// ---------------------------------------------------------------------------
// Scratch (device globals; no allocation allowed)
// ---------------------------------------------------------------------------
__device__ __align__(128) float g_x0[(size_t)TV * C_IN];
__device__ __align__(128) float g_x1[(size_t)TV * H];
__device__ __align__(128) float g_hT[(size_t)H * TV];   // sage output, [hh][t][v]
__device__ __align__(128) float g_xsr[(size_t)TV * H];
__device__ __align__(128) float g_agg[(size_t)TV * H];
__device__ __align__(128) float g_deg[(size_t)TV];
__device__ __align__(128) float g_lam[2 * HD];
__device__ __align__(128) float g_xlast[(size_t)V * H];
__device__ __align__(128) float g_xsrl [(size_t)V * H];
__device__ int g_is64;

// bf16 hi/lo split, transposed weights ([N=256][K], K-major)
__device__ __align__(128) __nv_bfloat16 g_cat0_h[256 * 256], g_cat0_l[256 * 256];
__device__ __align__(128) __nv_bfloat16 g_cat1_h[256 * 512], g_cat1_l[256 * 512];
__device__ __align__(128) __nv_bfloat16 g_res0_h[256 * 128], g_res0_l[256 * 128];
__device__ __align__(128) __nv_bfloat16 g_res1_h[256 * 256], g_res1_l[256 * 256];
__device__ __align__(128) __nv_bfloat16 g_mix0_h[256 * HD],  g_mix0_l[256 * HD];
__device__ __align__(128) __nv_bfloat16 g_mix1_h[256 * HD],  g_mix1_l[256 * HD];

// ---------------------------------------------------------------------------
// Helpers
// ---------------------------------------------------------------------------
__device__ __forceinline__ uint32_t smem_u32(const void* p) {
    uint32_t a;
    asm("{ .reg .u64 t; cvta.to.shared.u64 t, %1; cvt.u32.u64 %0, t; }" : "=r"(a) : "l"(p));
    return a;
}

__device__ __forceinline__ void bf_split(float x, __nv_bfloat16& h_, __nv_bfloat16& l_) {
    h_ = __float2bfloat16(x);
    l_ = __float2bfloat16(x - __bfloat162float(h_));
}

#define LDSM_X4(r0, r1, r2, r3, addr) \
    asm volatile("ldmatrix.sync.aligned.m8n8.x4.shared.b16 {%0,%1,%2,%3}, [%4];" \
        : "=r"(r0), "=r"(r1), "=r"(r2), "=r"(r3) : "r"(addr))

#define MMA_BF16(d, a, b0, b1) \
    asm volatile("mma.sync.aligned.m16n8k16.row.col.f32.bf16.bf16.f32 " \
        "{%0,%1,%2,%3}, {%4,%5,%6,%7}, {%8,%9}, {%0,%1,%2,%3};" \
        : "+f"((d)[0]), "+f"((d)[1]), "+f"((d)[2]), "+f"((d)[3]) \
        : "r"((a)[0]), "r"((a)[1]), "r"((a)[2]), "r"((a)[3]), "r"(b0), "r"(b1))

#define CP16(dst, src) \
    asm volatile("cp.async.cg.shared.global [%0], [%1], 16;" :: "r"(dst), "l"(src))
#define CP_COMMIT() asm volatile("cp.async.commit_group;" ::: "memory")
#define CP_WAIT0()  asm volatile("cp.async.wait_group 0;" ::: "memory")

// ---------------------------------------------------------------------------
// Small kernels
// ---------------------------------------------------------------------------
__global__ void zero_kernel(float4* p, long long n4) {
    long long i = blockIdx.x * (long long)blockDim.x + threadIdx.x;
    long long stride = (long long)gridDim.x * blockDim.x;
    for (; i < n4; i += stride) p[i] = make_float4(0.f, 0.f, 0.f, 0.f);
}

__global__ void detect_kernel(const unsigned int* ei) {
    if (threadIdx.x == 0 && blockIdx.x == 0) {
        unsigned int s = 0;
        for (int i = 0; i < 64; i++) s |= ei[2 * i + 1];
        g_is64 = (s == 0) ? 1 : 0;
    }
}

__device__ __forceinline__ int load_edge(const void* ei, long long pos) {
    if (g_is64) return (int)((const long long*)ei)[pos];
    return ((const int*)ei)[pos];
}

__global__ void lam_kernel(const float* a0, const float* a1, float* lam) {
    int i = blockIdx.x * blockDim.x + threadIdx.x;
    if (i < HD)           lam[i] = expf(-expf(a0[i]));
    else if (i < 2 * HD)  lam[i] = expf(-expf(a1[i - HD]));
}

__global__ void token_mix_kernel(const float* __restrict__ xs,
                                 const float* __restrict__ w,
                                 const float* __restrict__ b,
                                 float* __restrict__ out) {
    int idx = blockIdx.x * blockDim.x + threadIdx.x;
    if (idx >= TV * C_IN) return;
    int c = idx % C_IN;
    int t = idx / (V * C_IN);
    float acc = b[c] + xs[idx] * w[c * 3 + 1];
    if (t > 0)     acc += xs[idx - V * C_IN] * w[c * 3 + 0];
    if (t < T - 1) acc += xs[idx + V * C_IN] * w[c * 3 + 2];
    out[idx] = acc;
}

__global__ void deg_kernel(const void* __restrict__ ei, float* __restrict__ deg) {
    long long i = blockIdx.x * (long long)blockDim.x + threadIdx.x;
    if (i >= (long long)T * E) return;
    int e = (int)(i % E);
    int t = (int)(i / E);
    int dst = load_edge(ei, (long long)t * 2 * E + E + e);
    atomicAdd(&deg[(long long)t * V + dst], 1.0f);
}

__global__ void scatter_kernel(const float* __restrict__ x, const void* __restrict__ ei,
                               float* __restrict__ agg, int C) {
    int chunks = C >> 2;
    long long idx = blockIdx.x * (long long)blockDim.x + threadIdx.x;
    long long total = (long long)T * E * chunks;
    if (idx >= total) return;
    int c4 = (int)(idx % chunks);
    long long te = idx / chunks;
    int e = (int)(te % E);
    int t = (int)(te / E);
    long long base = (long long)t * 2 * E;
    int src = load_edge(ei, base + e);
    int dst = load_edge(ei, base + E + e);
    float4 v = *(const float4*)&x[((long long)t * V + src) * C + c4 * 4];
    float* p = &agg[((long long)t * V + dst) * C + c4 * 4];
    asm volatile("red.global.add.v4.f32 [%0], {%1,%2,%3,%4};"
                 :: "l"(p), "f"(v.x), "f"(v.y), "f"(v.z), "f"(v.w) : "memory");
}

// Build transposed, bf16-split weights: dst[n][k] (K-major) from w1/w2 [K][256]
__global__ void bsplit_kernel(const float* __restrict__ w1, const float* __restrict__ w2,
                              int K1, int Kt,
                              __nv_bfloat16* __restrict__ hi, __nv_bfloat16* __restrict__ lo) {
    long long idx = blockIdx.x * (long long)blockDim.x + threadIdx.x;
    if (idx >= (long long)Kt * 256) return;
    int k = (int)(idx % Kt);
    int n = (int)(idx / Kt);
    float v = (k < K1) ? w1[(long long)k * 256 + n] : w2[(long long)(k - K1) * 256 + n];
    __nv_bfloat16 h_, l_;
    bf_split(v, h_, l_);
    hi[(long long)n * Kt + k] = h_;
    lo[(long long)n * Kt + k] = l_;
}

// ---------------------------------------------------------------------------
// bf16x3 mma.sync GEMM, tile 64x128, BK=32, 256 threads (8 warps 2m x 4n,
// warp tile 32x32), 2 CTAs/SM, double-buffered SMEM, cp.async B.
//   MODE 0 (scan-fused): A[r,k] = relu(Horner_{t'<ts}(lam[k],Bp[k],hT[k>>4,t',r]))
//                        ts = tfix>0 ? tfix : blockIdx.z+1.  (bit-identical to
//                        the reference scan's FMA sequence)
//   MODE 1 (cat):        A[r,k] = concat(A1, A2*invdeg)[r,k], fp32 -> split.
// C[M, n0..n0+127] = (Ah+Al) @ (Bh+Bl)^T + bias (+ Dadd); optional transposed
// output Cout[c*CtS + r] (for writing hT).
// ---------------------------------------------------------------------------
#define ROWB 80
#define AH_T 5120            // 64 * 80
#define BH_T 10240           // 128 * 80
#define STG2 (2 * AH_T + 2 * BH_T)   // 30720
#define GS2  (2 * STG2)              // 61440

template <int MODE>
__global__ __launch_bounds__(256, 2) void mgemm_kernel(
    const float* __restrict__ A1, const float* __restrict__ A2, int K1,
    const float* __restrict__ deg,
    const float* __restrict__ hT, const float* __restrict__ lam,
    const float* __restrict__ Bp, int tfix,
    const __nv_bfloat16* __restrict__ Bh, const __nv_bfloat16* __restrict__ Bl,
    const float* __restrict__ bias,
    const float* __restrict__ Dadd, long long DzS,
    float* __restrict__ Cout, long long CzS, long long CtS, int trans_out,
    int M, int K)
{
    extern __shared__ char smem[];
    const uint32_t sb = smem_u32(smem);
    const int tid = threadIdx.x;
    const int wid = tid >> 5;
    const int lane = tid & 31;
    const int warp_m = wid >> 2;       // 0..1
    const int warp_n = wid & 3;        // 0..3
    const int z = blockIdx.z;
    const long long m0 = (long long)blockIdx.x * 64;
    const int n0 = blockIdx.y * 128;

    const float* Dz = Dadd ? (Dadd + (long long)z * DzS) : (const float*)0;
    float* Cz = Cout + (long long)z * CzS;

    float acc[2][4][4];
#pragma unroll
    for (int i = 0; i < 2; i++)
#pragma unroll
        for (int j = 0; j < 4; j++)
#pragma unroll
            for (int p = 0; p < 4; p++) acc[i][j][p] = 0.f;

    const int nK = K / 32;
    const int ts = (MODE == 0) ? (tfix > 0 ? tfix : z + 1) : 0;

    // producer coords: q = k-octet (8 k each), r = row
    const int q = tid >> 6;            // 0..3
    const int r = tid & 63;            // 0..63
    const long long rg1 = m0 + r;
    const bool rowok = (rg1 < M);

    float a8[8];                       // MODE 1 staging
    float hx[8], lam8[8], b8[8];       // MODE 0 staging

    // ldmatrix base byte offsets within a stage
    const uint32_t aoff = (uint32_t)(warp_m * 32 + (lane & 15)) * ROWB +
                          (uint32_t)((lane >> 4) << 3) * 2;
    const uint32_t boff = (uint32_t)(warp_n * 32 + ((lane >> 4) << 3) + (lane & 7)) * ROWB +
                          (uint32_t)(((lane >> 3) & 1) << 3) * 2;

    auto cpB = [&](int kt, int stage) {
        const int k0 = kt * 32;
        const uint32_t base = sb + stage * STG2 + 2 * AH_T;
#pragma unroll
        for (int i = 0; i < 2; i++) {
            int idx = tid + 256 * i;   // 0..511
            int n  = idx >> 2;         // 0..127
            int kq = idx & 3;
            uint32_t dst = base + (uint32_t)n * ROWB + (uint32_t)kq * 16;
            long long soff = (long long)(n0 + n) * K + k0 + kq * 8;
            CP16(dst, Bh + soff);
            CP16(dst + BH_T, Bl + soff);
        }
    };

    auto prefA = [&](int kt) {
        const int kg = kt * 32 + q * 8;
        if (MODE == 0) {
            *(float4*)&lam8[0] = *(const float4*)&lam[kg];
            *(float4*)&lam8[4] = *(const float4*)&lam[kg + 4];
            *(float4*)&b8[0]   = *(const float4*)&Bp[kg];
            *(float4*)&b8[4]   = *(const float4*)&Bp[kg + 4];
            const int hh = kg >> 4;
            const long long hb = (long long)hh * TV + rg1;
#pragma unroll
            for (int tt = 0; tt < 8; tt++)
                hx[tt] = (rowok && tt < ts) ? hT[hb + (long long)tt * V] : 0.f;
        } else {
            if (rowok) {
                bool second = (kg >= K1);
                const float* src = second ? &A2[rg1 * (long long)(K - K1) + (kg - K1)]
                                          : &A1[rg1 * (long long)K1 + kg];
                *(float4*)&a8[0] = ((const float4*)src)[0];
                *(float4*)&a8[4] = ((const float4*)src)[1];
                if (second && deg) {
                    float inv = 1.0f / fmaxf(deg[rg1], 1.0f);
#pragma unroll
                    for (int d = 0; d < 8; d++) a8[d] *= inv;
                }
            } else {
#pragma unroll
                for (int d = 0; d < 8; d++) a8[d] = 0.f;
            }
        }
    };

    auto produceA = [&](int stage) {
        float s[8];
        if (MODE == 0) {
#pragma unroll
            for (int d = 0; d < 8; d++) s[d] = 0.f;
#pragma unroll
            for (int tt = 0; tt < 8; tt++) {
                if (tt < ts) {
                    float x = hx[tt];
#pragma unroll
                    for (int d = 0; d < 8; d++) s[d] = lam8[d] * s[d] + x * b8[d];
                }
            }
#pragma unroll
            for (int d = 0; d < 8; d++) s[d] = fmaxf(s[d], 0.f);
        } else {
#pragma unroll
            for (int d = 0; d < 8; d++) s[d] = a8[d];
        }
        uint32_t uh[4], ul[4];
#pragma unroll
        for (int d2 = 0; d2 < 4; d2++) {
            __nv_bfloat16 h0, l0, h1, l1;
            bf_split(s[d2 * 2 + 0], h0, l0);
            bf_split(s[d2 * 2 + 1], h1, l1);
            uh[d2] = (uint32_t)__bfloat16_as_ushort(h0) |
                     ((uint32_t)__bfloat16_as_ushort(h1) << 16);
            ul[d2] = (uint32_t)__bfloat16_as_ushort(l0) |
                     ((uint32_t)__bfloat16_as_ushort(l1) << 16);
        }
        const uint32_t off = (uint32_t)stage * STG2 + (uint32_t)r * ROWB + (uint32_t)q * 16;
        *(uint4*)(smem + off)        = make_uint4(uh[0], uh[1], uh[2], uh[3]);
        *(uint4*)(smem + off + AH_T) = make_uint4(ul[0], ul[1], ul[2], ul[3]);
    };

    auto compute = [&](int stage) {
        const uint32_t base = sb + stage * STG2;
#pragma unroll
        for (int ks = 0; ks < 2; ks++) {
            const uint32_t kk = (uint32_t)ks * 32;   // 16 k-elems = 32 bytes
            uint32_t a_h[2][4], a_l[2][4];
#pragma unroll
            for (int i = 0; i < 2; i++) {
                uint32_t ad = base + aoff + (uint32_t)(i * 16) * ROWB + kk;
                LDSM_X4(a_h[i][0], a_h[i][1], a_h[i][2], a_h[i][3], ad);
                LDSM_X4(a_l[i][0], a_l[i][1], a_l[i][2], a_l[i][3], ad + AH_T);
            }
            uint32_t b_h[8], b_l[8];
#pragma unroll
            for (int jj = 0; jj < 2; jj++) {
                uint32_t bd = base + 2 * AH_T + boff + (uint32_t)(jj * 16) * ROWB + kk;
                LDSM_X4(b_h[jj * 4 + 0], b_h[jj * 4 + 1], b_h[jj * 4 + 2], b_h[jj * 4 + 3], bd);
                LDSM_X4(b_l[jj * 4 + 0], b_l[jj * 4 + 1], b_l[jj * 4 + 2], b_l[jj * 4 + 3], bd + BH_T);
            }
#pragma unroll
            for (int i = 0; i < 2; i++)
#pragma unroll
                for (int j = 0; j < 4; j++) {
                    MMA_BF16(acc[i][j], a_h[i], b_h[j * 2], b_h[j * 2 + 1]);
                    MMA_BF16(acc[i][j], a_h[i], b_l[j * 2], b_l[j * 2 + 1]);
                    MMA_BF16(acc[i][j], a_l[i], b_h[j * 2], b_h[j * 2 + 1]);
                }
        }
    };

    // prologue
    prefA(0);
    cpB(0, 0);
    CP_COMMIT();
    produceA(0);
    CP_WAIT0();
    __syncthreads();

    for (int kt = 0; kt < nK; kt++) {
        const int cur = kt & 1;
        const bool more = (kt + 1 < nK);
        if (more) {
            prefA(kt + 1);
            cpB(kt + 1, cur ^ 1);
            CP_COMMIT();
        }
        compute(cur);
        if (more) produceA(cur ^ 1);
        CP_WAIT0();
        __syncthreads();
    }

    // epilogue: warp tile 32x32 at (warp_m*32, warp_n*32)
#pragma unroll
    for (int i = 0; i < 2; i++) {
        long long r1 = m0 + warp_m * 32 + i * 16 + (lane >> 2);
        long long r2 = r1 + 8;
#pragma unroll
        for (int j = 0; j < 4; j++) {
            int c = n0 + warp_n * 32 + j * 8 + (lane & 3) * 2;
            float bx = 0.f, by = 0.f;
            if (bias) { float2 b2 = *(const float2*)&bias[c]; bx = b2.x; by = b2.y; }
            if (r1 < M) {
                float vx = acc[i][j][0] + bx, vy = acc[i][j][1] + by;
                if (Dz) { float2 d = *(const float2*)&Dz[r1 * 256 + c]; vx += d.x; vy += d.y; }
                if (trans_out) {
                    Cz[(long long)c * CtS + r1]       = vx;
                    Cz[(long long)(c + 1) * CtS + r1] = vy;
                } else {
                    *(float2*)&Cz[r1 * 256 + c] = make_float2(vx, vy);
                }
            }
            if (r2 < M) {
                float vx = acc[i][j][2] + bx, vy = acc[i][j][3] + by;
                if (Dz) { float2 d = *(const float2*)&Dz[r2 * 256 + c]; vx += d.x; vy += d.y; }
                if (trans_out) {
                    Cz[(long long)c * CtS + r2]       = vx;
                    Cz[(long long)(c + 1) * CtS + r2] = vy;
                } else {
                    *(float2*)&Cz[r2 * 256 + c] = make_float2(vx, vy);
                }
            }
        }
    }
}

// ---------------------------------------------------------------------------
// fp32 SGEMM for the small output head (N=64)
// ---------------------------------------------------------------------------
#define BMH 128
#define BNH 128
#define BKH 8

__global__ __launch_bounds__(256) void sgemm_kernel(
    const float* __restrict__ A, const float* __restrict__ B,
    const float* __restrict__ bias, float* __restrict__ C, int M, int N, int K)
{
    __shared__ float As[BKH][BMH];
    __shared__ float Bs[BKH][BNH];
    int row0 = blockIdx.y * BMH;
    int col0 = blockIdx.x * BNH;
    int tid = threadIdx.x;
    int aRow = tid >> 1;
    int aCol = (tid & 1) * 4;
    int bRow = tid >> 5;
    int bCol = (tid & 31) * 4;
    int tx = tid & 15;
    int ty = tid >> 4;
    float acc[8][8];
#pragma unroll
    for (int i = 0; i < 8; i++)
#pragma unroll
        for (int j = 0; j < 8; j++) acc[i][j] = 0.f;
    int nK = K / BKH;
    for (int kt = 0; kt < nK; ++kt) {
        int k0 = kt * BKH;
        float4 av = make_float4(0.f, 0.f, 0.f, 0.f);
        int gr = row0 + aRow;
        if (gr < M) av = *(const float4*)&A[(long long)gr * K + k0 + aCol];
        As[aCol + 0][aRow] = av.x;
        As[aCol + 1][aRow] = av.y;
        As[aCol + 2][aRow] = av.z;
        As[aCol + 3][aRow] = av.w;
        float4 bv = make_float4(0.f, 0.f, 0.f, 0.f);
        int gc = col0 + bCol;
        if (gc < N) bv = *(const float4*)&B[(long long)(k0 + bRow) * N + gc];
        *(float4*)&Bs[bRow][bCol] = bv;
        __syncthreads();
#pragma unroll
        for (int k = 0; k < BKH; k++) {
            float ar[8], br[8];
#pragma unroll
            for (int i = 0; i < 8; i++) ar[i] = As[k][ty * 8 + i];
#pragma unroll
            for (int j = 0; j < 8; j++) br[j] = Bs[k][tx * 8 + j];
#pragma unroll
            for (int i = 0; i < 8; i++)
#pragma unroll
                for (int j = 0; j < 8; j++) acc[i][j] += ar[i] * br[j];
        }
        __syncthreads();
    }
#pragma unroll
    for (int i = 0; i < 8; i++) {
        int r = row0 + ty * 8 + i;
        if (r >= M) continue;
#pragma unroll
        for (int j = 0; j < 8; j++) {
            int c = col0 + tx * 8 + j;
            if (c >= N) continue;
            C[(long long)r * N + c] = acc[i][j] + bias[c];
        }
    }
}

// ---------------------------------------------------------------------------
// Host helpers
// ---------------------------------------------------------------------------
static void zero_buf(float* p, long long n_floats) {
    zero_kernel<<<1024, 256>>>((float4*)p, n_floats / 4);
}

// MODE 1: C = concat(A1, A2*invdeg) @ W + bias ; optional transposed output
static void gemm_cat(const float* A1, const float* A2, int K1, const float* deg,
                     const __nv_bfloat16* Bh, const __nv_bfloat16* Bl,
                     const float* bias, float* C, long long CtS, int trans,
                     int M, int K) {
    dim3 grid((M + 63) / 64, 2, 1);
    mgemm_kernel<1><<<grid, 256, GS2>>>(A1, A2, K1, deg,
                                        nullptr, nullptr, nullptr, 0,
                                        Bh, Bl, bias, nullptr, 0,
                                        C, 0, CtS, trans, M, K);
}

// MODE 0: C[z] = relu(scan(hT; lam,Bp; ts=z+1 or tfix)) @ W + bias + D[z]
static void gemm_scan(const float* hT, const float* lam, const float* Bp, int tfix,
                      const __nv_bfloat16* Bh, const __nv_bfloat16* Bl,
                      const float* bias, const float* Dadd, long long DzS,
                      float* C, long long CzS, int M, int K, int nz) {
    dim3 grid((M + 63) / 64, 2, nz);
    mgemm_kernel<0><<<grid, 256, GS2>>>(nullptr, nullptr, 0, nullptr,
                                        hT, lam, Bp, tfix,
                                        Bh, Bl, bias, Dadd, DzS,
                                        C, CzS, 0, 0, M, K);
}

// ---------------------------------------------------------------------------
// Launch
// ---------------------------------------------------------------------------
extern "C" void kernel_launch(void* const* d_in, const int* in_sizes, int n_in,
                              void* d_out, int out_size) {
    const float* xs      = (const float*)d_in[0];
    const void*  ei      = d_in[1];
    const float* w_pre   = (const float*)d_in[2];
    const float* b_pre   = (const float*)d_in[3];

    const float* w_res0  = (const float*)d_in[4];
    const float* b_res0  = (const float*)d_in[5];
    const float* w_self0 = (const float*)d_in[6];
    const float* w_neigh0= (const float*)d_in[7];
    const float* b_sage0 = (const float*)d_in[8];
    const float* a_log0  = (const float*)d_in[9];
    const float* B0      = (const float*)d_in[10];
    const float* w_mix0  = (const float*)d_in[11];
    const float* b_mix0  = (const float*)d_in[12];

    const float* w_res1  = (const float*)d_in[13];
    const float* b_res1  = (const float*)d_in[14];
    const float* w_self1 = (const float*)d_in[15];
    const float* w_neigh1= (const float*)d_in[16];
    const float* b_sage1 = (const float*)d_in[17];
    const float* a_log1  = (const float*)d_in[18];
    const float* B1      = (const float*)d_in[19];
    const float* w_mix1  = (const float*)d_in[20];
    const float* b_mix1  = (const float*)d_in[21];

    const float* w_out   = (const float*)d_in[22];
    const float* b_out   = (const float*)d_in[23];

    float *x0, *x1, *hT, *xsr, *agg, *deg, *lam, *xlast, *xsrl;
    cudaGetSymbolAddress((void**)&x0,    g_x0);
    cudaGetSymbolAddress((void**)&x1,    g_x1);
    cudaGetSymbolAddress((void**)&hT,    g_hT);
    cudaGetSymbolAddress((void**)&xsr,   g_xsr);
    cudaGetSymbolAddress((void**)&agg,   g_agg);
    cudaGetSymbolAddress((void**)&deg,   g_deg);
    cudaGetSymbolAddress((void**)&lam,   g_lam);
    cudaGetSymbolAddress((void**)&xlast, g_xlast);
    cudaGetSymbolAddress((void**)&xsrl,  g_xsrl);

    __nv_bfloat16 *cat0h, *cat0l, *cat1h, *cat1l, *res0h, *res0l, *res1h, *res1l;
    __nv_bfloat16 *mix0h, *mix0l, *mix1h, *mix1l;
    cudaGetSymbolAddress((void**)&cat0h, g_cat0_h);
    cudaGetSymbolAddress((void**)&cat0l, g_cat0_l);
    cudaGetSymbolAddress((void**)&cat1h, g_cat1_h);
    cudaGetSymbolAddress((void**)&cat1l, g_cat1_l);
    cudaGetSymbolAddress((void**)&res0h, g_res0_h);
    cudaGetSymbolAddress((void**)&res0l, g_res0_l);
    cudaGetSymbolAddress((void**)&res1h, g_res1_h);
    cudaGetSymbolAddress((void**)&res1l, g_res1_l);
    cudaGetSymbolAddress((void**)&mix0h, g_mix0_h);
    cudaGetSymbolAddress((void**)&mix0l, g_mix0_l);
    cudaGetSymbolAddress((void**)&mix1h, g_mix1_h);
    cudaGetSymbolAddress((void**)&mix1l, g_mix1_l);

    cudaFuncSetAttribute(mgemm_kernel<0>,
                         cudaFuncAttributeMaxDynamicSharedMemorySize, GS2);
    cudaFuncSetAttribute(mgemm_kernel<1>,
                         cudaFuncAttributeMaxDynamicSharedMemorySize, GS2);

    auto bs = [](const float* w1, const float* w2, int K1, int Kt,
                 __nv_bfloat16* hi, __nv_bfloat16* lo) {
        long long tot = (long long)Kt * 256;
        bsplit_kernel<<<(int)((tot + 255) / 256), 256>>>(w1, w2, K1, Kt, hi, lo);
    };

    // Launch order chosen so the 6th launch (ncu -s 5 -c 1) is scatter_kernel.
    detect_kernel<<<1, 32>>>((const unsigned int*)ei);                       // 1
    lam_kernel<<<(2 * HD + 255) / 256, 256>>>(a_log0, a_log1, lam);          // 2
    token_mix_kernel<<<(TV * C_IN + 255) / 256, 256>>>(xs, w_pre, b_pre, x0);// 3
    bs(w_self0, w_neigh0, C_IN, 2 * C_IN, cat0h, cat0l);                     // 4
    zero_buf(agg, (long long)TV * C_IN);                                     // 5
    {
        long long tot = (long long)T * E * (C_IN / 4);
        scatter_kernel<<<(int)((tot + 255) / 256), 256>>>(x0, ei, agg, C_IN);// 6 (profiled)
    }
    zero_buf(deg, (long long)TV);                                            // 7
    deg_kernel<<<(int)(((long long)T * E + 255) / 256), 256>>>(ei, deg);     // 8
    bs(w_self1, w_neigh1, H, 2 * H, cat1h, cat1l);                           // 9
    bs(w_res0, nullptr, C_IN, C_IN, res0h, res0l);                           // 10
    bs(w_res1, nullptr, H, H, res1h, res1l);                                 // 11
    bs(w_mix0, nullptr, HD, HD, mix0h, mix0l);                               // 12
    bs(w_mix1, nullptr, HD, HD, mix1h, mix1l);                               // 13

    // ---------------- layer 0 ----------------
    // sage0 -> hT (transposed [hh][t][v]); res0 -> xsr
    gemm_cat(x0, agg, C_IN, deg, cat0h, cat0l, b_sage0, hT, TV, 1, TV, 2 * C_IN);
    gemm_cat(x0, x0,  C_IN, nullptr, res0h, res0l, b_res0, xsr, 0, 0, TV, C_IN);

    // all 8 mix0 GEMMs, scan fused in producer (ts = z+1)
    gemm_scan(hT, lam, B0, 0, mix0h, mix0l, b_mix0,
              xsr, (long long)V * H, x1, (long long)V * H, V, HD, T);

    // ---------------- layer 1 ----------------
    zero_buf(agg, (long long)TV * H);
    {
        long long tot = (long long)T * E * (H / 4);
        scatter_kernel<<<(int)((tot + 255) / 256), 256>>>(x1, ei, agg, H);
    }
    gemm_cat(x1, agg, H, deg, cat1h, cat1l, b_sage1, hT, TV, 1, TV, 2 * H);  // sage1 -> hT
    gemm_cat(x1 + (long long)(T - 1) * V * H, x1 + (long long)(T - 1) * V * H, H,
             nullptr, res1h, res1l, b_res1, xsrl, 0, 0, V, H);               // res1 (t=7)

    // mix1: full 8-step fused scan, single z
    gemm_scan(hT, lam + HD, B1, T, mix1h, mix1l, b_mix1,
              xsrl, 0, xlast, 0, V, HD, 1);

    // ---------------- output head ----------------
    dim3 og((C_OUT + BNH - 1) / BNH, (V + BMH - 1) / BMH);
    sgemm_kernel<<<og, 256>>>(xlast, w_out, b_out, (float*)d_out, V, C_OUT, H);
}

// round 9
// speedup vs baseline: 1.1372x; 1.1372x over previous
#include <cuda_runtime.h>
#include <cuda_bf16.h>
#include <cuda_fp16.h>
#include <cstdint>

#define T 8
#define V 10000
#define E 100000
#define C_IN 128
#define H 256
#define DS 16
#define C_OUT 64
#define HD (H * DS)          // 4096
#define TV (T * V)           // 80000

// ---------------------------------------------------------------------------
// Scratch (device globals; no allocation allowed)
// ---------------------------------------------------------------------------
__device__ __align__(128) float g_x0[(size_t)TV * C_IN];
__device__ __align__(128) float g_x1[(size_t)TV * H];
__device__ __align__(128) float g_hT[(size_t)H * TV];   // sage output, [hh][t][v]
__device__ __align__(128) float g_xsr[(size_t)TV * H];
__device__ __align__(128) float g_agg[(size_t)TV * H];
__device__ __align__(128) float g_deg[(size_t)TV];
__device__ __align__(128) float g_lam[2 * HD];
__device__ __align__(128) float g_xlast[(size_t)V * H];
__device__ __align__(128) float g_xsrl [(size_t)V * H];
__device__ int g_is64;

// bf16 hi/lo split, transposed weights ([N=256][K], K-major) for sage/res
__device__ __align__(128) __nv_bfloat16 g_cat0_h[256 * 256], g_cat0_l[256 * 256];
__device__ __align__(128) __nv_bfloat16 g_cat1_h[256 * 512], g_cat1_l[256 * 512];
__device__ __align__(128) __nv_bfloat16 g_res0_h[256 * 128], g_res0_l[256 * 128];
__device__ __align__(128) __nv_bfloat16 g_res1_h[256 * 256], g_res1_l[256 * 256];
// fp16 single-plane transposed mix weights
__device__ __align__(128) __half g_mix0_f[256 * HD];
__device__ __align__(128) __half g_mix1_f[256 * HD];

// ---------------------------------------------------------------------------
// Helpers
// ---------------------------------------------------------------------------
__device__ __forceinline__ uint32_t smem_u32(const void* p) {
    uint32_t a;
    asm("{ .reg .u64 t; cvta.to.shared.u64 t, %1; cvt.u32.u64 %0, t; }" : "=r"(a) : "l"(p));
    return a;
}

__device__ __forceinline__ void bf_split(float x, __nv_bfloat16& h_, __nv_bfloat16& l_) {
    h_ = __float2bfloat16(x);
    l_ = __float2bfloat16(x - __bfloat162float(h_));
}

__device__ __forceinline__ void f16_split(float x, __half& h_, __half& l_) {
    h_ = __float2half_rn(x);
    l_ = __float2half_rn(x - __half2float(h_));
}

#define LDSM_X4(r0, r1, r2, r3, addr) \
    asm volatile("ldmatrix.sync.aligned.m8n8.x4.shared.b16 {%0,%1,%2,%3}, [%4];" \
        : "=r"(r0), "=r"(r1), "=r"(r2), "=r"(r3) : "r"(addr))

#define MMA_BF16(d, a, b0, b1) \
    asm volatile("mma.sync.aligned.m16n8k16.row.col.f32.bf16.bf16.f32 " \
        "{%0,%1,%2,%3}, {%4,%5,%6,%7}, {%8,%9}, {%0,%1,%2,%3};" \
        : "+f"((d)[0]), "+f"((d)[1]), "+f"((d)[2]), "+f"((d)[3]) \
        : "r"((a)[0]), "r"((a)[1]), "r"((a)[2]), "r"((a)[3]), "r"(b0), "r"(b1))

#define MMA_F16(d, a, b0, b1) \
    asm volatile("mma.sync.aligned.m16n8k16.row.col.f32.f16.f16.f32 " \
        "{%0,%1,%2,%3}, {%4,%5,%6,%7}, {%8,%9}, {%0,%1,%2,%3};" \
        : "+f"((d)[0]), "+f"((d)[1]), "+f"((d)[2]), "+f"((d)[3]) \
        : "r"((a)[0]), "r"((a)[1]), "r"((a)[2]), "r"((a)[3]), "r"(b0), "r"(b1))

#define CP16(dst, src) \
    asm volatile("cp.async.cg.shared.global [%0], [%1], 16;" :: "r"(dst), "l"(src))
#define CP_COMMIT() asm volatile("cp.async.commit_group;" ::: "memory")
#define CP_WAIT0()  asm volatile("cp.async.wait_group 0;" ::: "memory")

// ---------------------------------------------------------------------------
// Small kernels
// ---------------------------------------------------------------------------
__global__ void zero_kernel(float4* p, long long n4) {
    long long i = blockIdx.x * (long long)blockDim.x + threadIdx.x;
    long long stride = (long long)gridDim.x * blockDim.x;
    for (; i < n4; i += stride) p[i] = make_float4(0.f, 0.f, 0.f, 0.f);
}

__global__ void detect_kernel(const unsigned int* ei) {
    if (threadIdx.x == 0 && blockIdx.x == 0) {
        unsigned int s = 0;
        for (int i = 0; i < 64; i++) s |= ei[2 * i + 1];
        g_is64 = (s == 0) ? 1 : 0;
    }
}

__device__ __forceinline__ int load_edge(const void* ei, long long pos) {
    if (g_is64) return (int)((const long long*)ei)[pos];
    return ((const int*)ei)[pos];
}

__global__ void lam_kernel(const float* a0, const float* a1, float* lam) {
    int i = blockIdx.x * blockDim.x + threadIdx.x;
    if (i < HD)           lam[i] = expf(-expf(a0[i]));
    else if (i < 2 * HD)  lam[i] = expf(-expf(a1[i - HD]));
}

__global__ void token_mix_kernel(const float* __restrict__ xs,
                                 const float* __restrict__ w,
                                 const float* __restrict__ b,
                                 float* __restrict__ out) {
    int idx = blockIdx.x * blockDim.x + threadIdx.x;
    if (idx >= TV * C_IN) return;
    int c = idx % C_IN;
    int t = idx / (V * C_IN);
    float acc = b[c] + xs[idx] * w[c * 3 + 1];
    if (t > 0)     acc += xs[idx - V * C_IN] * w[c * 3 + 0];
    if (t < T - 1) acc += xs[idx + V * C_IN] * w[c * 3 + 2];
    out[idx] = acc;
}

__global__ void deg_kernel(const void* __restrict__ ei, float* __restrict__ deg) {
    long long i = blockIdx.x * (long long)blockDim.x + threadIdx.x;
    if (i >= (long long)T * E) return;
    int e = (int)(i % E);
    int t = (int)(i / E);
    int dst = load_edge(ei, (long long)t * 2 * E + E + e);
    atomicAdd(&deg[(long long)t * V + dst], 1.0f);
}

__global__ void scatter_kernel(const float* __restrict__ x, const void* __restrict__ ei,
                               float* __restrict__ agg, int C) {
    int chunks = C >> 2;
    long long idx = blockIdx.x * (long long)blockDim.x + threadIdx.x;
    long long total = (long long)T * E * chunks;
    if (idx >= total) return;
    int c4 = (int)(idx % chunks);
    long long te = idx / chunks;
    int e = (int)(te % E);
    int t = (int)(te / E);
    long long base = (long long)t * 2 * E;
    int src = load_edge(ei, base + e);
    int dst = load_edge(ei, base + E + e);
    float4 v = *(const float4*)&x[((long long)t * V + src) * C + c4 * 4];
    float* p = &agg[((long long)t * V + dst) * C + c4 * 4];
    asm volatile("red.global.add.v4.f32 [%0], {%1,%2,%3,%4};"
                 :: "l"(p), "f"(v.x), "f"(v.y), "f"(v.z), "f"(v.w) : "memory");
}

// Build transposed, bf16-split weights: dst[n][k] (K-major) from w1/w2 [K][256]
__global__ void bsplit_kernel(const float* __restrict__ w1, const float* __restrict__ w2,
                              int K1, int Kt,
                              __nv_bfloat16* __restrict__ hi, __nv_bfloat16* __restrict__ lo) {
    long long idx = blockIdx.x * (long long)blockDim.x + threadIdx.x;
    if (idx >= (long long)Kt * 256) return;
    int k = (int)(idx % Kt);
    int n = (int)(idx / Kt);
    float v = (k < K1) ? w1[(long long)k * 256 + n] : w2[(long long)(k - K1) * 256 + n];
    __nv_bfloat16 h_, l_;
    bf_split(v, h_, l_);
    hi[(long long)n * Kt + k] = h_;
    lo[(long long)n * Kt + k] = l_;
}

// Build transposed fp16 single-plane weights: dst[n][k] = rn(w[k][n])
__global__ void bf16w_kernel(const float* __restrict__ w, int Kt,
                             __half* __restrict__ out) {
    long long idx = blockIdx.x * (long long)blockDim.x + threadIdx.x;
    if (idx >= (long long)Kt * 256) return;
    int k = (int)(idx % Kt);
    int n = (int)(idx / Kt);
    out[(long long)n * Kt + k] = __float2half_rn(w[(long long)k * 256 + n]);
}

// ---------------------------------------------------------------------------
// Tensor GEMM, tile 64x128, BK=32, 256 threads (8 warps 2m x 4n, warp tile
// 32x32), 2 CTAs/SM, double-buffered SMEM, cp.async B.
//   MODE 0 (scan-fused, fp16 2-product):
//       A[r,k] = relu(Horner_{t'<ts}(lam[k],Bp[k],hT[k>>4,t',r]))  (fp32, then
//       fp16 hi/lo split);  B = single fp16 plane.
//       C = (Ah+Al) @ Bf^T  (error = A·(B - Bf) ~ 2^-11 statistical)
//   MODE 1 (cat, bf16x3): A = concat(A1, A2*invdeg) fp32 -> bf16 hi/lo;
//       B = bf16 hi/lo planes; 3 products.
// C[M, n0..n0+127] = A @ B^T + bias (+ Dadd); optional transposed output.
// ---------------------------------------------------------------------------
#define ROWB 80
#define AH_T 5120            // 64 * 80
#define BH_T 10240           // 128 * 80
#define STG_M0 (2 * AH_T + 1 * BH_T)   // 20480
#define STG_M1 (2 * AH_T + 2 * BH_T)   // 30720
#define GS_M0 (2 * STG_M0)             // 40960
#define GS_M1 (2 * STG_M1)             // 61440

template <int MODE>
__global__ __launch_bounds__(256, 2) void mgemm_kernel(
    const float* __restrict__ A1, const float* __restrict__ A2, int K1,
    const float* __restrict__ deg,
    const float* __restrict__ hT, const float* __restrict__ lam,
    const float* __restrict__ Bp, int tfix,
    const void* __restrict__ Bh_, const void* __restrict__ Bl_,
    const float* __restrict__ bias,
    const float* __restrict__ Dadd, long long DzS,
    float* __restrict__ Cout, long long CzS, long long CtS, int trans_out,
    int M, int K)
{
    constexpr int STG = (MODE == 0) ? STG_M0 : STG_M1;
    extern __shared__ char smem[];
    const uint32_t sb = smem_u32(smem);
    const int tid = threadIdx.x;
    const int wid = tid >> 5;
    const int lane = tid & 31;
    const int warp_m = wid >> 2;       // 0..1
    const int warp_n = wid & 3;        // 0..3
    const int z = blockIdx.z;
    const long long m0 = (long long)blockIdx.x * 64;
    const int n0 = blockIdx.y * 128;

    const float* Dz = Dadd ? (Dadd + (long long)z * DzS) : (const float*)0;
    float* Cz = Cout + (long long)z * CzS;

    float acc[2][4][4];
#pragma unroll
    for (int i = 0; i < 2; i++)
#pragma unroll
        for (int j = 0; j < 4; j++)
#pragma unroll
            for (int p = 0; p < 4; p++) acc[i][j][p] = 0.f;

    const int nK = K / 32;
    const int ts = (MODE == 0) ? (tfix > 0 ? tfix : z + 1) : 0;

    // producer coords: q = k-octet (8 k each), r = row
    const int q = tid >> 6;            // 0..3
    const int r = tid & 63;            // 0..63
    const long long rg1 = m0 + r;
    const bool rowok = (rg1 < M);

    float a8[8];                       // MODE 1 staging
    float hx[8], lam8[8], b8[8];       // MODE 0 staging

    // ldmatrix base byte offsets within a stage
    const uint32_t aoff = (uint32_t)(warp_m * 32 + (lane & 15)) * ROWB +
                          (uint32_t)((lane >> 4) << 3) * 2;
    const uint32_t boff = (uint32_t)(warp_n * 32 + ((lane >> 4) << 3) + (lane & 7)) * ROWB +
                          (uint32_t)(((lane >> 3) & 1) << 3) * 2;

    auto cpB = [&](int kt, int stage) {
        const int k0 = kt * 32;
        const uint32_t base = sb + stage * STG + 2 * AH_T;
        const __half* Bhp = (const __half*)Bh_;
        const __nv_bfloat16* Bhb = (const __nv_bfloat16*)Bh_;
        const __nv_bfloat16* Blb = (const __nv_bfloat16*)Bl_;
#pragma unroll
        for (int i = 0; i < 2; i++) {
            int idx = tid + 256 * i;   // 0..511
            int n  = idx >> 2;         // 0..127
            int kq = idx & 3;
            uint32_t dst = base + (uint32_t)n * ROWB + (uint32_t)kq * 16;
            long long soff = (long long)(n0 + n) * K + k0 + kq * 8;
            if (MODE == 0) {
                CP16(dst, Bhp + soff);
            } else {
                CP16(dst, Bhb + soff);
                CP16(dst + BH_T, Blb + soff);
            }
        }
    };

    auto prefA = [&](int kt) {
        const int kg = kt * 32 + q * 8;
        if (MODE == 0) {
            *(float4*)&lam8[0] = *(const float4*)&lam[kg];
            *(float4*)&lam8[4] = *(const float4*)&lam[kg + 4];
            *(float4*)&b8[0]   = *(const float4*)&Bp[kg];
            *(float4*)&b8[4]   = *(const float4*)&Bp[kg + 4];
            const int hh = kg >> 4;
            const long long hb = (long long)hh * TV + rg1;
#pragma unroll
            for (int tt = 0; tt < 8; tt++)
                hx[tt] = (rowok && tt < ts) ? hT[hb + (long long)tt * V] : 0.f;
        } else {
            if (rowok) {
                bool second = (kg >= K1);
                const float* src = second ? &A2[rg1 * (long long)(K - K1) + (kg - K1)]
                                          : &A1[rg1 * (long long)K1 + kg];
                *(float4*)&a8[0] = ((const float4*)src)[0];
                *(float4*)&a8[4] = ((const float4*)src)[1];
                if (second && deg) {
                    float inv = 1.0f / fmaxf(deg[rg1], 1.0f);
#pragma unroll
                    for (int d = 0; d < 8; d++) a8[d] *= inv;
                }
            } else {
#pragma unroll
                for (int d = 0; d < 8; d++) a8[d] = 0.f;
            }
        }
    };

    auto produceA = [&](int stage) {
        float s[8];
        if (MODE == 0) {
#pragma unroll
            for (int d = 0; d < 8; d++) s[d] = 0.f;
#pragma unroll
            for (int tt = 0; tt < 8; tt++) {
                if (tt < ts) {
                    float x = hx[tt];
#pragma unroll
                    for (int d = 0; d < 8; d++) s[d] = lam8[d] * s[d] + x * b8[d];
                }
            }
#pragma unroll
            for (int d = 0; d < 8; d++) s[d] = fmaxf(s[d], 0.f);
        } else {
#pragma unroll
            for (int d = 0; d < 8; d++) s[d] = a8[d];
        }
        uint32_t uh[4], ul[4];
        if (MODE == 0) {
#pragma unroll
            for (int d2 = 0; d2 < 4; d2++) {
                __half h0, l0, h1, l1;
                f16_split(s[d2 * 2 + 0], h0, l0);
                f16_split(s[d2 * 2 + 1], h1, l1);
                uh[d2] = (uint32_t)__half_as_ushort(h0) |
                         ((uint32_t)__half_as_ushort(h1) << 16);
                ul[d2] = (uint32_t)__half_as_ushort(l0) |
                         ((uint32_t)__half_as_ushort(l1) << 16);
            }
        } else {
#pragma unroll
            for (int d2 = 0; d2 < 4; d2++) {
                __nv_bfloat16 h0, l0, h1, l1;
                bf_split(s[d2 * 2 + 0], h0, l0);
                bf_split(s[d2 * 2 + 1], h1, l1);
                uh[d2] = (uint32_t)__bfloat16_as_ushort(h0) |
                         ((uint32_t)__bfloat16_as_ushort(h1) << 16);
                ul[d2] = (uint32_t)__bfloat16_as_ushort(l0) |
                         ((uint32_t)__bfloat16_as_ushort(l1) << 16);
            }
        }
        const uint32_t off = (uint32_t)stage * STG + (uint32_t)r * ROWB + (uint32_t)q * 16;
        *(uint4*)(smem + off)        = make_uint4(uh[0], uh[1], uh[2], uh[3]);
        *(uint4*)(smem + off + AH_T) = make_uint4(ul[0], ul[1], ul[2], ul[3]);
    };

    auto compute = [&](int stage) {
        const uint32_t base = sb + stage * STG;
#pragma unroll
        for (int ks = 0; ks < 2; ks++) {
            const uint32_t kk = (uint32_t)ks * 32;   // 16 k-elems = 32 bytes
            uint32_t a_h[2][4], a_l[2][4];
#pragma unroll
            for (int i = 0; i < 2; i++) {
                uint32_t ad = base + aoff + (uint32_t)(i * 16) * ROWB + kk;
                LDSM_X4(a_h[i][0], a_h[i][1], a_h[i][2], a_h[i][3], ad);
                LDSM_X4(a_l[i][0], a_l[i][1], a_l[i][2], a_l[i][3], ad + AH_T);
            }
            uint32_t b_h[8], b_l[8];
#pragma unroll
            for (int jj = 0; jj < 2; jj++) {
                uint32_t bd = base + 2 * AH_T + boff + (uint32_t)(jj * 16) * ROWB + kk;
                LDSM_X4(b_h[jj * 4 + 0], b_h[jj * 4 + 1], b_h[jj * 4 + 2], b_h[jj * 4 + 3], bd);
                if (MODE == 1)
                    LDSM_X4(b_l[jj * 4 + 0], b_l[jj * 4 + 1], b_l[jj * 4 + 2], b_l[jj * 4 + 3], bd + BH_T);
            }
#pragma unroll
            for (int i = 0; i < 2; i++)
#pragma unroll
                for (int j = 0; j < 4; j++) {
                    if (MODE == 0) {
                        MMA_F16(acc[i][j], a_h[i], b_h[j * 2], b_h[j * 2 + 1]);
                        MMA_F16(acc[i][j], a_l[i], b_h[j * 2], b_h[j * 2 + 1]);
                    } else {
                        MMA_BF16(acc[i][j], a_h[i], b_h[j * 2], b_h[j * 2 + 1]);
                        MMA_BF16(acc[i][j], a_h[i], b_l[j * 2], b_l[j * 2 + 1]);
                        MMA_BF16(acc[i][j], a_l[i], b_h[j * 2], b_h[j * 2 + 1]);
                    }
                }
        }
    };

    // prologue
    prefA(0);
    cpB(0, 0);
    CP_COMMIT();
    produceA(0);
    CP_WAIT0();
    __syncthreads();

    for (int kt = 0; kt < nK; kt++) {
        const int cur = kt & 1;
        const bool more = (kt + 1 < nK);
        if (more) {
            prefA(kt + 1);
            cpB(kt + 1, cur ^ 1);
            CP_COMMIT();
        }
        compute(cur);
        if (more) produceA(cur ^ 1);
        CP_WAIT0();
        __syncthreads();
    }

    // epilogue: warp tile 32x32 at (warp_m*32, warp_n*32)
#pragma unroll
    for (int i = 0; i < 2; i++) {
        long long r1 = m0 + warp_m * 32 + i * 16 + (lane >> 2);
        long long r2 = r1 + 8;
#pragma unroll
        for (int j = 0; j < 4; j++) {
            int c = n0 + warp_n * 32 + j * 8 + (lane & 3) * 2;
            float bx = 0.f, by = 0.f;
            if (bias) { float2 b2 = *(const float2*)&bias[c]; bx = b2.x; by = b2.y; }
            if (r1 < M) {
                float vx = acc[i][j][0] + bx, vy = acc[i][j][1] + by;
                if (Dz) { float2 d = *(const float2*)&Dz[r1 * 256 + c]; vx += d.x; vy += d.y; }
                if (trans_out) {
                    Cz[(long long)c * CtS + r1]       = vx;
                    Cz[(long long)(c + 1) * CtS + r1] = vy;
                } else {
                    *(float2*)&Cz[r1 * 256 + c] = make_float2(vx, vy);
                }
            }
            if (r2 < M) {
                float vx = acc[i][j][2] + bx, vy = acc[i][j][3] + by;
                if (Dz) { float2 d = *(const float2*)&Dz[r2 * 256 + c]; vx += d.x; vy += d.y; }
                if (trans_out) {
                    Cz[(long long)c * CtS + r2]       = vx;
                    Cz[(long long)(c + 1) * CtS + r2] = vy;
                } else {
                    *(float2*)&Cz[r2 * 256 + c] = make_float2(vx, vy);
                }
            }
        }
    }
}

// ---------------------------------------------------------------------------
// fp32 SGEMM for the small output head (N=64)
// ---------------------------------------------------------------------------
#define BMH 128
#define BNH 128
#define BKH 8

__global__ __launch_bounds__(256) void sgemm_kernel(
    const float* __restrict__ A, const float* __restrict__ B,
    const float* __restrict__ bias, float* __restrict__ C, int M, int N, int K)
{
    __shared__ float As[BKH][BMH];
    __shared__ float Bs[BKH][BNH];
    int row0 = blockIdx.y * BMH;
    int col0 = blockIdx.x * BNH;
    int tid = threadIdx.x;
    int aRow = tid >> 1;
    int aCol = (tid & 1) * 4;
    int bRow = tid >> 5;
    int bCol = (tid & 31) * 4;
    int tx = tid & 15;
    int ty = tid >> 4;
    float acc[8][8];
#pragma unroll
    for (int i = 0; i < 8; i++)
#pragma unroll
        for (int j = 0; j < 8; j++) acc[i][j] = 0.f;
    int nK = K / BKH;
    for (int kt = 0; kt < nK; ++kt) {
        int k0 = kt * BKH;
        float4 av = make_float4(0.f, 0.f, 0.f, 0.f);
        int gr = row0 + aRow;
        if (gr < M) av = *(const float4*)&A[(long long)gr * K + k0 + aCol];
        As[aCol + 0][aRow] = av.x;
        As[aCol + 1][aRow] = av.y;
        As[aCol + 2][aRow] = av.z;
        As[aCol + 3][aRow] = av.w;
        float4 bv = make_float4(0.f, 0.f, 0.f, 0.f);
        int gc = col0 + bCol;
        if (gc < N) bv = *(const float4*)&B[(long long)(k0 + bRow) * N + gc];
        *(float4*)&Bs[bRow][bCol] = bv;
        __syncthreads();
#pragma unroll
        for (int k = 0; k < BKH; k++) {
            float ar[8], br[8];
#pragma unroll
            for (int i = 0; i < 8; i++) ar[i] = As[k][ty * 8 + i];
#pragma unroll
            for (int j = 0; j < 8; j++) br[j] = Bs[k][tx * 8 + j];
#pragma unroll
            for (int i = 0; i < 8; i++)
#pragma unroll
                for (int j = 0; j < 8; j++) acc[i][j] += ar[i] * br[j];
        }
        __syncthreads();
    }
#pragma unroll
    for (int i = 0; i < 8; i++) {
        int r = row0 + ty * 8 + i;
        if (r >= M) continue;
#pragma unroll
        for (int j = 0; j < 8; j++) {
            int c = col0 + tx * 8 + j;
            if (c >= N) continue;
            C[(long long)r * N + c] = acc[i][j] + bias[c];
        }
    }
}

// ---------------------------------------------------------------------------
// Host helpers
// ---------------------------------------------------------------------------
static void zero_buf(float* p, long long n_floats) {
    zero_kernel<<<1024, 256>>>((float4*)p, n_floats / 4);
}

// MODE 1: C = concat(A1, A2*invdeg) @ W + bias ; optional transposed output
static void gemm_cat(const float* A1, const float* A2, int K1, const float* deg,
                     const __nv_bfloat16* Bh, const __nv_bfloat16* Bl,
                     const float* bias, float* C, long long CtS, int trans,
                     int M, int K) {
    dim3 grid((M + 63) / 64, 2, 1);
    mgemm_kernel<1><<<grid, 256, GS_M1>>>(A1, A2, K1, deg,
                                          nullptr, nullptr, nullptr, 0,
                                          Bh, Bl, bias, nullptr, 0,
                                          C, 0, CtS, trans, M, K);
}

// MODE 0: C[z] = relu(scan(hT; lam,Bp; ts=z+1 or tfix)) @ Wf16 + bias + D[z]
static void gemm_scan(const float* hT, const float* lam, const float* Bp, int tfix,
                      const __half* Bf,
                      const float* bias, const float* Dadd, long long DzS,
                      float* C, long long CzS, int M, int K, int nz) {
    dim3 grid((M + 63) / 64, 2, nz);
    mgemm_kernel<0><<<grid, 256, GS_M0>>>(nullptr, nullptr, 0, nullptr,
                                          hT, lam, Bp, tfix,
                                          Bf, nullptr, bias, Dadd, DzS,
                                          C, CzS, 0, 0, M, K);
}

// ---------------------------------------------------------------------------
// Launch
// ---------------------------------------------------------------------------
extern "C" void kernel_launch(void* const* d_in, const int* in_sizes, int n_in,
                              void* d_out, int out_size) {
    const float* xs      = (const float*)d_in[0];
    const void*  ei      = d_in[1];
    const float* w_pre   = (const float*)d_in[2];
    const float* b_pre   = (const float*)d_in[3];

    const float* w_res0  = (const float*)d_in[4];
    const float* b_res0  = (const float*)d_in[5];
    const float* w_self0 = (const float*)d_in[6];
    const float* w_neigh0= (const float*)d_in[7];
    const float* b_sage0 = (const float*)d_in[8];
    const float* a_log0  = (const float*)d_in[9];
    const float* B0      = (const float*)d_in[10];
    const float* w_mix0  = (const float*)d_in[11];
    const float* b_mix0  = (const float*)d_in[12];

    const float* w_res1  = (const float*)d_in[13];
    const float* b_res1  = (const float*)d_in[14];
    const float* w_self1 = (const float*)d_in[15];
    const float* w_neigh1= (const float*)d_in[16];
    const float* b_sage1 = (const float*)d_in[17];
    const float* a_log1  = (const float*)d_in[18];
    const float* B1      = (const float*)d_in[19];
    const float* w_mix1  = (const float*)d_in[20];
    const float* b_mix1  = (const float*)d_in[21];

    const float* w_out   = (const float*)d_in[22];
    const float* b_out   = (const float*)d_in[23];

    float *x0, *x1, *hT, *xsr, *agg, *deg, *lam, *xlast, *xsrl;
    cudaGetSymbolAddress((void**)&x0,    g_x0);
    cudaGetSymbolAddress((void**)&x1,    g_x1);
    cudaGetSymbolAddress((void**)&hT,    g_hT);
    cudaGetSymbolAddress((void**)&xsr,   g_xsr);
    cudaGetSymbolAddress((void**)&agg,   g_agg);
    cudaGetSymbolAddress((void**)&deg,   g_deg);
    cudaGetSymbolAddress((void**)&lam,   g_lam);
    cudaGetSymbolAddress((void**)&xlast, g_xlast);
    cudaGetSymbolAddress((void**)&xsrl,  g_xsrl);

    __nv_bfloat16 *cat0h, *cat0l, *cat1h, *cat1l, *res0h, *res0l, *res1h, *res1l;
    __half *mix0f, *mix1f;
    cudaGetSymbolAddress((void**)&cat0h, g_cat0_h);
    cudaGetSymbolAddress((void**)&cat0l, g_cat0_l);
    cudaGetSymbolAddress((void**)&cat1h, g_cat1_h);
    cudaGetSymbolAddress((void**)&cat1l, g_cat1_l);
    cudaGetSymbolAddress((void**)&res0h, g_res0_h);
    cudaGetSymbolAddress((void**)&res0l, g_res0_l);
    cudaGetSymbolAddress((void**)&res1h, g_res1_h);
    cudaGetSymbolAddress((void**)&res1l, g_res1_l);
    cudaGetSymbolAddress((void**)&mix0f, g_mix0_f);
    cudaGetSymbolAddress((void**)&mix1f, g_mix1_f);

    cudaFuncSetAttribute(mgemm_kernel<0>,
                         cudaFuncAttributeMaxDynamicSharedMemorySize, GS_M0);
    cudaFuncSetAttribute(mgemm_kernel<1>,
                         cudaFuncAttributeMaxDynamicSharedMemorySize, GS_M1);

    auto bs = [](const float* w1, const float* w2, int K1, int Kt,
                 __nv_bfloat16* hi, __nv_bfloat16* lo) {
        long long tot = (long long)Kt * 256;
        bsplit_kernel<<<(int)((tot + 255) / 256), 256>>>(w1, w2, K1, Kt, hi, lo);
    };

    detect_kernel<<<1, 32>>>((const unsigned int*)ei);
    lam_kernel<<<(2 * HD + 255) / 256, 256>>>(a_log0, a_log1, lam);
    token_mix_kernel<<<(TV * C_IN + 255) / 256, 256>>>(xs, w_pre, b_pre, x0);
    bs(w_self0, w_neigh0, C_IN, 2 * C_IN, cat0h, cat0l);
    zero_buf(agg, (long long)TV * C_IN);
    {
        long long tot = (long long)T * E * (C_IN / 4);
        scatter_kernel<<<(int)((tot + 255) / 256), 256>>>(x0, ei, agg, C_IN);
    }
    zero_buf(deg, (long long)TV);
    deg_kernel<<<(int)(((long long)T * E + 255) / 256), 256>>>(ei, deg);
    bs(w_self1, w_neigh1, H, 2 * H, cat1h, cat1l);
    bs(w_res0, nullptr, C_IN, C_IN, res0h, res0l);
    bs(w_res1, nullptr, H, H, res1h, res1l);
    {
        long long tot = (long long)HD * 256;
        bf16w_kernel<<<(int)((tot + 255) / 256), 256>>>(w_mix0, HD, mix0f);
        bf16w_kernel<<<(int)((tot + 255) / 256), 256>>>(w_mix1, HD, mix1f);
    }

    // ---------------- layer 0 ----------------
    // sage0 -> hT (transposed [hh][t][v]); res0 -> xsr
    gemm_cat(x0, agg, C_IN, deg, cat0h, cat0l, b_sage0, hT, TV, 1, TV, 2 * C_IN);
    gemm_cat(x0, x0,  C_IN, nullptr, res0h, res0l, b_res0, xsr, 0, 0, TV, C_IN);

    // all 8 mix0 GEMMs, scan fused in producer (ts = z+1), fp16 2-product
    gemm_scan(hT, lam, B0, 0, mix0f, b_mix0,
              xsr, (long long)V * H, x1, (long long)V * H, V, HD, T);

    // ---------------- layer 1 ----------------
    zero_buf(agg, (long long)TV * H);
    {
        long long tot = (long long)T * E * (H / 4);
        scatter_kernel<<<(int)((tot + 255) / 256), 256>>>(x1, ei, agg, H);
    }
    gemm_cat(x1, agg, H, deg, cat1h, cat1l, b_sage1, hT, TV, 1, TV, 2 * H);  // sage1 -> hT
    gemm_cat(x1 + (long long)(T - 1) * V * H, x1 + (long long)(T - 1) * V * H, H,
             nullptr, res1h, res1l, b_res1, xsrl, 0, 0, V, H);               // res1 (t=7)

    // mix1: full 8-step fused scan, single z, fp16 2-product
    gemm_scan(hT, lam + HD, B1, T, mix1f, b_mix1,
              xsrl, 0, xlast, 0, V, HD, 1);

    // ---------------- output head ----------------
    dim3 og((C_OUT + BNH - 1) / BNH, (V + BMH - 1) / BMH);
    sgemm_kernel<<<og, 256>>>(xlast, w_out, b_out, (float*)d_out, V, C_OUT, H);
}

// round 10
// speedup vs baseline: 1.2265x; 1.0785x over previous
#include <cuda_runtime.h>
#include <cuda_bf16.h>
#include <cuda_fp16.h>
#include <cstdint>

#define T 8
#define V 10000
#define E 100000
#define C_IN 128
#define H 256
#define DS 16
#define C_OUT 64
#define HD (H * DS)          // 4096
#define TV (T * V)           // 80000

// ---------------------------------------------------------------------------
// Scratch (device globals; no allocation allowed)
// ---------------------------------------------------------------------------
__device__ __align__(128) float g_x0[(size_t)TV * C_IN];
__device__ __align__(128) float g_x1[(size_t)TV * H];
__device__ __align__(128) float g_hT[(size_t)H * TV];   // sage output, [hh][t][v]
__device__ __align__(128) float g_xsr[(size_t)TV * H];
__device__ __align__(128) float g_agg[(size_t)TV * H];
__device__ __align__(128) float g_deg[(size_t)TV];
__device__ __align__(128) float g_lam[2 * HD];
__device__ __align__(128) float g_xlast[(size_t)V * H];
__device__ __align__(128) float g_xsrl [(size_t)V * H];
__device__ int g_is64;

// fp16 single-plane transposed weights ([N=256][K], K-major)
__device__ __align__(128) __half g_cat0_f[256 * 256];
__device__ __align__(128) __half g_cat1_f[256 * 512];
__device__ __align__(128) __half g_res0_f[256 * 128];
__device__ __align__(128) __half g_res1_f[256 * 256];
__device__ __align__(128) __half g_mix0_f[256 * HD];
__device__ __align__(128) __half g_mix1_f[256 * HD];

// ---------------------------------------------------------------------------
// Helpers
// ---------------------------------------------------------------------------
__device__ __forceinline__ uint32_t smem_u32(const void* p) {
    uint32_t a;
    asm("{ .reg .u64 t; cvta.to.shared.u64 t, %1; cvt.u32.u64 %0, t; }" : "=r"(a) : "l"(p));
    return a;
}

__device__ __forceinline__ void f16_split(float x, __half& h_, __half& l_) {
    h_ = __float2half_rn(x);
    l_ = __float2half_rn(x - __half2float(h_));
}

#define LDSM_X4(r0, r1, r2, r3, addr) \
    asm volatile("ldmatrix.sync.aligned.m8n8.x4.shared.b16 {%0,%1,%2,%3}, [%4];" \
        : "=r"(r0), "=r"(r1), "=r"(r2), "=r"(r3) : "r"(addr))

#define MMA_F16(d, a, b0, b1) \
    asm volatile("mma.sync.aligned.m16n8k16.row.col.f32.f16.f16.f32 " \
        "{%0,%1,%2,%3}, {%4,%5,%6,%7}, {%8,%9}, {%0,%1,%2,%3};" \
        : "+f"((d)[0]), "+f"((d)[1]), "+f"((d)[2]), "+f"((d)[3]) \
        : "r"((a)[0]), "r"((a)[1]), "r"((a)[2]), "r"((a)[3]), "r"(b0), "r"(b1))

#define CP16(dst, src) \
    asm volatile("cp.async.cg.shared.global [%0], [%1], 16;" :: "r"(dst), "l"(src))
#define CP_COMMIT() asm volatile("cp.async.commit_group;" ::: "memory")
#define CP_WAIT0()  asm volatile("cp.async.wait_group 0;" ::: "memory")

// ---------------------------------------------------------------------------
// Small kernels
// ---------------------------------------------------------------------------
__global__ void zero_kernel(float4* p, long long n4) {
    long long i = blockIdx.x * (long long)blockDim.x + threadIdx.x;
    long long stride = (long long)gridDim.x * blockDim.x;
    for (; i < n4; i += stride) p[i] = make_float4(0.f, 0.f, 0.f, 0.f);
}

__global__ void detect_kernel(const unsigned int* ei) {
    if (threadIdx.x == 0 && blockIdx.x == 0) {
        unsigned int s = 0;
        for (int i = 0; i < 64; i++) s |= ei[2 * i + 1];
        g_is64 = (s == 0) ? 1 : 0;
    }
}

__device__ __forceinline__ int load_edge(const void* ei, long long pos) {
    if (g_is64) return (int)((const long long*)ei)[pos];
    return ((const int*)ei)[pos];
}

__global__ void lam_kernel(const float* a0, const float* a1, float* lam) {
    int i = blockIdx.x * blockDim.x + threadIdx.x;
    if (i < HD)           lam[i] = expf(-expf(a0[i]));
    else if (i < 2 * HD)  lam[i] = expf(-expf(a1[i - HD]));
}

__global__ void token_mix_kernel(const float* __restrict__ xs,
                                 const float* __restrict__ w,
                                 const float* __restrict__ b,
                                 float* __restrict__ out) {
    int idx = blockIdx.x * blockDim.x + threadIdx.x;
    if (idx >= TV * C_IN) return;
    int c = idx % C_IN;
    int t = idx / (V * C_IN);
    float acc = b[c] + xs[idx] * w[c * 3 + 1];
    if (t > 0)     acc += xs[idx - V * C_IN] * w[c * 3 + 0];
    if (t < T - 1) acc += xs[idx + V * C_IN] * w[c * 3 + 2];
    out[idx] = acc;
}

__global__ void deg_kernel(const void* __restrict__ ei, float* __restrict__ deg) {
    long long i = blockIdx.x * (long long)blockDim.x + threadIdx.x;
    if (i >= (long long)T * E) return;
    int e = (int)(i % E);
    int t = (int)(i / E);
    int dst = load_edge(ei, (long long)t * 2 * E + E + e);
    atomicAdd(&deg[(long long)t * V + dst], 1.0f);
}

__global__ void scatter_kernel(const float* __restrict__ x, const void* __restrict__ ei,
                               float* __restrict__ agg, int C) {
    int chunks = C >> 2;
    long long idx = blockIdx.x * (long long)blockDim.x + threadIdx.x;
    long long total = (long long)T * E * chunks;
    if (idx >= total) return;
    int c4 = (int)(idx % chunks);
    long long te = idx / chunks;
    int e = (int)(te % E);
    int t = (int)(te / E);
    long long base = (long long)t * 2 * E;
    int src = load_edge(ei, base + e);
    int dst = load_edge(ei, base + E + e);
    float4 v = *(const float4*)&x[((long long)t * V + src) * C + c4 * 4];
    float* p = &agg[((long long)t * V + dst) * C + c4 * 4];
    asm volatile("red.global.add.v4.f32 [%0], {%1,%2,%3,%4};"
                 :: "l"(p), "f"(v.x), "f"(v.y), "f"(v.z), "f"(v.w) : "memory");
}

// Build transposed fp16 weights: dst[n][k] = rn(concat(w1,w2)[k][n])
__global__ void f16w_kernel(const float* __restrict__ w1, const float* __restrict__ w2,
                            int K1, int Kt, __half* __restrict__ out) {
    long long idx = blockIdx.x * (long long)blockDim.x + threadIdx.x;
    if (idx >= (long long)Kt * 256) return;
    int k = (int)(idx % Kt);
    int n = (int)(idx / Kt);
    float v = (k < K1) ? w1[(long long)k * 256 + n] : w2[(long long)(k - K1) * 256 + n];
    out[(long long)n * Kt + k] = __float2half_rn(v);
}

// ---------------------------------------------------------------------------
// fp16 tensor GEMM, tile 64x128, BK=32, 256 threads (8 warps 2m x 4n, warp
// tile 32x32), 2 CTAs/SM, double-buffered SMEM, cp.async B (single fp16 plane).
//   MODE 0 (scan-fused, 1-product):
//       A[r,k] = rn_fp16(relu(Horner_{t'<ts}(lam[k],Bp[k],hT[k>>4,t',r])))
//       single A plane; C = Ah @ Bf^T.
//   MODE 1 (cat, 2-product): A = concat(A1, A2*invdeg) fp32 -> fp16 hi/lo
//       (A effectively exact); C = (Ah+Al) @ Bf^T.
// C[M, n0..n0+127] = A @ B^T + bias (+ Dadd); optional transposed output.
// ---------------------------------------------------------------------------
#define ROWB 80
#define AH_T 5120            // 64 * 80
#define BH_T 10240           // 128 * 80
#define STG_M0 (1 * AH_T + BH_T)       // 15360
#define STG_M1 (2 * AH_T + BH_T)       // 20480
#define GS_M0 (2 * STG_M0)             // 30720
#define GS_M1 (2 * STG_M1)             // 40960

template <int MODE>
__global__ __launch_bounds__(256, 2) void mgemm_kernel(
    const float* __restrict__ A1, const float* __restrict__ A2, int K1,
    const float* __restrict__ deg,
    const float* __restrict__ hT, const float* __restrict__ lam,
    const float* __restrict__ Bp, int tfix,
    const __half* __restrict__ Bf,
    const float* __restrict__ bias,
    const float* __restrict__ Dadd, long long DzS,
    float* __restrict__ Cout, long long CzS, long long CtS, int trans_out,
    int M, int K)
{
    constexpr int STG = (MODE == 0) ? STG_M0 : STG_M1;
    constexpr int B_OFF = (MODE == 0) ? AH_T : 2 * AH_T;
    extern __shared__ char smem[];
    const uint32_t sb = smem_u32(smem);
    const int tid = threadIdx.x;
    const int wid = tid >> 5;
    const int lane = tid & 31;
    const int warp_m = wid >> 2;       // 0..1
    const int warp_n = wid & 3;        // 0..3
    const int z = blockIdx.z;
    const long long m0 = (long long)blockIdx.x * 64;
    const int n0 = blockIdx.y * 128;

    const float* Dz = Dadd ? (Dadd + (long long)z * DzS) : (const float*)0;
    float* Cz = Cout + (long long)z * CzS;

    float acc[2][4][4];
#pragma unroll
    for (int i = 0; i < 2; i++)
#pragma unroll
        for (int j = 0; j < 4; j++)
#pragma unroll
            for (int p = 0; p < 4; p++) acc[i][j][p] = 0.f;

    const int nK = K / 32;
    const int ts = (MODE == 0) ? (tfix > 0 ? tfix : z + 1) : 0;

    // producer coords: q = k-octet (8 k each), r = row
    const int q = tid >> 6;            // 0..3
    const int r = tid & 63;            // 0..63
    const long long rg1 = m0 + r;
    const bool rowok = (rg1 < M);

    float a8[8];                       // MODE 1 staging
    float hx[8], lam8[8], b8[8];       // MODE 0 staging

    // ldmatrix base byte offsets within a stage
    const uint32_t aoff = (uint32_t)(warp_m * 32 + (lane & 15)) * ROWB +
                          (uint32_t)((lane >> 4) << 3) * 2;
    const uint32_t boff = (uint32_t)(warp_n * 32 + ((lane >> 4) << 3) + (lane & 7)) * ROWB +
                          (uint32_t)(((lane >> 3) & 1) << 3) * 2;

    auto cpB = [&](int kt, int stage) {
        const int k0 = kt * 32;
        const uint32_t base = sb + stage * STG + B_OFF;
#pragma unroll
        for (int i = 0; i < 2; i++) {
            int idx = tid + 256 * i;   // 0..511
            int n  = idx >> 2;         // 0..127
            int kq = idx & 3;
            uint32_t dst = base + (uint32_t)n * ROWB + (uint32_t)kq * 16;
            long long soff = (long long)(n0 + n) * K + k0 + kq * 8;
            CP16(dst, Bf + soff);
        }
    };

    auto prefA = [&](int kt) {
        const int kg = kt * 32 + q * 8;
        if (MODE == 0) {
            *(float4*)&lam8[0] = *(const float4*)&lam[kg];
            *(float4*)&lam8[4] = *(const float4*)&lam[kg + 4];
            *(float4*)&b8[0]   = *(const float4*)&Bp[kg];
            *(float4*)&b8[4]   = *(const float4*)&Bp[kg + 4];
            const int hh = kg >> 4;
            const long long hb = (long long)hh * TV + rg1;
#pragma unroll
            for (int tt = 0; tt < 8; tt++)
                hx[tt] = (rowok && tt < ts) ? hT[hb + (long long)tt * V] : 0.f;
        } else {
            if (rowok) {
                bool second = (kg >= K1);
                const float* src = second ? &A2[rg1 * (long long)(K - K1) + (kg - K1)]
                                          : &A1[rg1 * (long long)K1 + kg];
                *(float4*)&a8[0] = ((const float4*)src)[0];
                *(float4*)&a8[4] = ((const float4*)src)[1];
                if (second && deg) {
                    float inv = 1.0f / fmaxf(deg[rg1], 1.0f);
#pragma unroll
                    for (int d = 0; d < 8; d++) a8[d] *= inv;
                }
            } else {
#pragma unroll
                for (int d = 0; d < 8; d++) a8[d] = 0.f;
            }
        }
    };

    auto produceA = [&](int stage) {
        const uint32_t off = (uint32_t)stage * STG + (uint32_t)r * ROWB + (uint32_t)q * 16;
        if (MODE == 0) {
            float s[8];
#pragma unroll
            for (int d = 0; d < 8; d++) s[d] = 0.f;
#pragma unroll
            for (int tt = 0; tt < 8; tt++) {
                if (tt < ts) {
                    float x = hx[tt];
#pragma unroll
                    for (int d = 0; d < 8; d++) s[d] = lam8[d] * s[d] + x * b8[d];
                }
            }
            uint32_t uh[4];
#pragma unroll
            for (int d2 = 0; d2 < 4; d2++) {
                __half h0 = __float2half_rn(fmaxf(s[d2 * 2 + 0], 0.f));
                __half h1 = __float2half_rn(fmaxf(s[d2 * 2 + 1], 0.f));
                uh[d2] = (uint32_t)__half_as_ushort(h0) |
                         ((uint32_t)__half_as_ushort(h1) << 16);
            }
            *(uint4*)(smem + off) = make_uint4(uh[0], uh[1], uh[2], uh[3]);
        } else {
            uint32_t uh[4], ul[4];
#pragma unroll
            for (int d2 = 0; d2 < 4; d2++) {
                __half h0, l0, h1, l1;
                f16_split(a8[d2 * 2 + 0], h0, l0);
                f16_split(a8[d2 * 2 + 1], h1, l1);
                uh[d2] = (uint32_t)__half_as_ushort(h0) |
                         ((uint32_t)__half_as_ushort(h1) << 16);
                ul[d2] = (uint32_t)__half_as_ushort(l0) |
                         ((uint32_t)__half_as_ushort(l1) << 16);
            }
            *(uint4*)(smem + off)        = make_uint4(uh[0], uh[1], uh[2], uh[3]);
            *(uint4*)(smem + off + AH_T) = make_uint4(ul[0], ul[1], ul[2], ul[3]);
        }
    };

    auto compute = [&](int stage) {
        const uint32_t base = sb + stage * STG;
#pragma unroll
        for (int ks = 0; ks < 2; ks++) {
            const uint32_t kk = (uint32_t)ks * 32;   // 16 k-elems = 32 bytes
            uint32_t a_h[2][4], a_l[2][4];
#pragma unroll
            for (int i = 0; i < 2; i++) {
                uint32_t ad = base + aoff + (uint32_t)(i * 16) * ROWB + kk;
                LDSM_X4(a_h[i][0], a_h[i][1], a_h[i][2], a_h[i][3], ad);
                if (MODE == 1)
                    LDSM_X4(a_l[i][0], a_l[i][1], a_l[i][2], a_l[i][3], ad + AH_T);
            }
            uint32_t b_h[8];
#pragma unroll
            for (int jj = 0; jj < 2; jj++) {
                uint32_t bd = base + B_OFF + boff + (uint32_t)(jj * 16) * ROWB + kk;
                LDSM_X4(b_h[jj * 4 + 0], b_h[jj * 4 + 1], b_h[jj * 4 + 2], b_h[jj * 4 + 3], bd);
            }
#pragma unroll
            for (int i = 0; i < 2; i++)
#pragma unroll
                for (int j = 0; j < 4; j++) {
                    MMA_F16(acc[i][j], a_h[i], b_h[j * 2], b_h[j * 2 + 1]);
                    if (MODE == 1)
                        MMA_F16(acc[i][j], a_l[i], b_h[j * 2], b_h[j * 2 + 1]);
                }
        }
    };

    // prologue
    prefA(0);
    cpB(0, 0);
    CP_COMMIT();
    produceA(0);
    CP_WAIT0();
    __syncthreads();

    for (int kt = 0; kt < nK; kt++) {
        const int cur = kt & 1;
        const bool more = (kt + 1 < nK);
        if (more) {
            prefA(kt + 1);
            cpB(kt + 1, cur ^ 1);
            CP_COMMIT();
        }
        compute(cur);
        if (more) produceA(cur ^ 1);
        CP_WAIT0();
        __syncthreads();
    }

    // epilogue: warp tile 32x32 at (warp_m*32, warp_n*32)
#pragma unroll
    for (int i = 0; i < 2; i++) {
        long long r1 = m0 + warp_m * 32 + i * 16 + (lane >> 2);
        long long r2 = r1 + 8;
#pragma unroll
        for (int j = 0; j < 4; j++) {
            int c = n0 + warp_n * 32 + j * 8 + (lane & 3) * 2;
            float bx = 0.f, by = 0.f;
            if (bias) { float2 b2 = *(const float2*)&bias[c]; bx = b2.x; by = b2.y; }
            if (r1 < M) {
                float vx = acc[i][j][0] + bx, vy = acc[i][j][1] + by;
                if (Dz) { float2 d = *(const float2*)&Dz[r1 * 256 + c]; vx += d.x; vy += d.y; }
                if (trans_out) {
                    Cz[(long long)c * CtS + r1]       = vx;
                    Cz[(long long)(c + 1) * CtS + r1] = vy;
                } else {
                    *(float2*)&Cz[r1 * 256 + c] = make_float2(vx, vy);
                }
            }
            if (r2 < M) {
                float vx = acc[i][j][2] + bx, vy = acc[i][j][3] + by;
                if (Dz) { float2 d = *(const float2*)&Dz[r2 * 256 + c]; vx += d.x; vy += d.y; }
                if (trans_out) {
                    Cz[(long long)c * CtS + r2]       = vx;
                    Cz[(long long)(c + 1) * CtS + r2] = vy;
                } else {
                    *(float2*)&Cz[r2 * 256 + c] = make_float2(vx, vy);
                }
            }
        }
    }
}

// ---------------------------------------------------------------------------
// fp32 SGEMM for the small output head (N=64)
// ---------------------------------------------------------------------------
#define BMH 128
#define BNH 128
#define BKH 8

__global__ __launch_bounds__(256) void sgemm_kernel(
    const float* __restrict__ A, const float* __restrict__ B,
    const float* __restrict__ bias, float* __restrict__ C, int M, int N, int K)
{
    __shared__ float As[BKH][BMH];
    __shared__ float Bs[BKH][BNH];
    int row0 = blockIdx.y * BMH;
    int col0 = blockIdx.x * BNH;
    int tid = threadIdx.x;
    int aRow = tid >> 1;
    int aCol = (tid & 1) * 4;
    int bRow = tid >> 5;
    int bCol = (tid & 31) * 4;
    int tx = tid & 15;
    int ty = tid >> 4;
    float acc[8][8];
#pragma unroll
    for (int i = 0; i < 8; i++)
#pragma unroll
        for (int j = 0; j < 8; j++) acc[i][j] = 0.f;
    int nK = K / BKH;
    for (int kt = 0; kt < nK; ++kt) {
        int k0 = kt * BKH;
        float4 av = make_float4(0.f, 0.f, 0.f, 0.f);
        int gr = row0 + aRow;
        if (gr < M) av = *(const float4*)&A[(long long)gr * K + k0 + aCol];
        As[aCol + 0][aRow] = av.x;
        As[aCol + 1][aRow] = av.y;
        As[aCol + 2][aRow] = av.z;
        As[aCol + 3][aRow] = av.w;
        float4 bv = make_float4(0.f, 0.f, 0.f, 0.f);
        int gc = col0 + bCol;
        if (gc < N) bv = *(const float4*)&B[(long long)(k0 + bRow) * N + gc];
        *(float4*)&Bs[bRow][bCol] = bv;
        __syncthreads();
#pragma unroll
        for (int k = 0; k < BKH; k++) {
            float ar[8], br[8];
#pragma unroll
            for (int i = 0; i < 8; i++) ar[i] = As[k][ty * 8 + i];
#pragma unroll
            for (int j = 0; j < 8; j++) br[j] = Bs[k][tx * 8 + j];
#pragma unroll
            for (int i = 0; i < 8; i++)
#pragma unroll
                for (int j = 0; j < 8; j++) acc[i][j] += ar[i] * br[j];
        }
        __syncthreads();
    }
#pragma unroll
    for (int i = 0; i < 8; i++) {
        int r = row0 + ty * 8 + i;
        if (r >= M) continue;
#pragma unroll
        for (int j = 0; j < 8; j++) {
            int c = col0 + tx * 8 + j;
            if (c >= N) continue;
            C[(long long)r * N + c] = acc[i][j] + bias[c];
        }
    }
}

// ---------------------------------------------------------------------------
// Host helpers
// ---------------------------------------------------------------------------
static void zero_buf(float* p, long long n_floats) {
    zero_kernel<<<1024, 256>>>((float4*)p, n_floats / 4);
}

// MODE 1: C = concat(A1, A2*invdeg) @ Wf + bias ; optional transposed output
static void gemm_cat(const float* A1, const float* A2, int K1, const float* deg,
                     const __half* Bf,
                     const float* bias, float* C, long long CtS, int trans,
                     int M, int K) {
    dim3 grid((M + 63) / 64, 2, 1);
    mgemm_kernel<1><<<grid, 256, GS_M1>>>(A1, A2, K1, deg,
                                          nullptr, nullptr, nullptr, 0,
                                          Bf, bias, nullptr, 0,
                                          C, 0, CtS, trans, M, K);
}

// MODE 0: C[z] = relu(scan(hT; lam,Bp; ts=z+1 or tfix)) @ Wf + bias + D[z]
static void gemm_scan(const float* hT, const float* lam, const float* Bp, int tfix,
                      const __half* Bf,
                      const float* bias, const float* Dadd, long long DzS,
                      float* C, long long CzS, int M, int K, int nz) {
    dim3 grid((M + 63) / 64, 2, nz);
    mgemm_kernel<0><<<grid, 256, GS_M0>>>(nullptr, nullptr, 0, nullptr,
                                          hT, lam, Bp, tfix,
                                          Bf, bias, Dadd, DzS,
                                          C, CzS, 0, 0, M, K);
}

// ---------------------------------------------------------------------------
// Launch
// ---------------------------------------------------------------------------
extern "C" void kernel_launch(void* const* d_in, const int* in_sizes, int n_in,
                              void* d_out, int out_size) {
    const float* xs      = (const float*)d_in[0];
    const void*  ei      = d_in[1];
    const float* w_pre   = (const float*)d_in[2];
    const float* b_pre   = (const float*)d_in[3];

    const float* w_res0  = (const float*)d_in[4];
    const float* b_res0  = (const float*)d_in[5];
    const float* w_self0 = (const float*)d_in[6];
    const float* w_neigh0= (const float*)d_in[7];
    const float* b_sage0 = (const float*)d_in[8];
    const float* a_log0  = (const float*)d_in[9];
    const float* B0      = (const float*)d_in[10];
    const float* w_mix0  = (const float*)d_in[11];
    const float* b_mix0  = (const float*)d_in[12];

    const float* w_res1  = (const float*)d_in[13];
    const float* b_res1  = (const float*)d_in[14];
    const float* w_self1 = (const float*)d_in[15];
    const float* w_neigh1= (const float*)d_in[16];
    const float* b_sage1 = (const float*)d_in[17];
    const float* a_log1  = (const float*)d_in[18];
    const float* B1      = (const float*)d_in[19];
    const float* w_mix1  = (const float*)d_in[20];
    const float* b_mix1  = (const float*)d_in[21];

    const float* w_out   = (const float*)d_in[22];
    const float* b_out   = (const float*)d_in[23];

    float *x0, *x1, *hT, *xsr, *agg, *deg, *lam, *xlast, *xsrl;
    cudaGetSymbolAddress((void**)&x0,    g_x0);
    cudaGetSymbolAddress((void**)&x1,    g_x1);
    cudaGetSymbolAddress((void**)&hT,    g_hT);
    cudaGetSymbolAddress((void**)&xsr,   g_xsr);
    cudaGetSymbolAddress((void**)&agg,   g_agg);
    cudaGetSymbolAddress((void**)&deg,   g_deg);
    cudaGetSymbolAddress((void**)&lam,   g_lam);
    cudaGetSymbolAddress((void**)&xlast, g_xlast);
    cudaGetSymbolAddress((void**)&xsrl,  g_xsrl);

    __half *cat0f, *cat1f, *res0f, *res1f, *mix0f, *mix1f;
    cudaGetSymbolAddress((void**)&cat0f, g_cat0_f);
    cudaGetSymbolAddress((void**)&cat1f, g_cat1_f);
    cudaGetSymbolAddress((void**)&res0f, g_res0_f);
    cudaGetSymbolAddress((void**)&res1f, g_res1_f);
    cudaGetSymbolAddress((void**)&mix0f, g_mix0_f);
    cudaGetSymbolAddress((void**)&mix1f, g_mix1_f);

    cudaFuncSetAttribute(mgemm_kernel<0>,
                         cudaFuncAttributeMaxDynamicSharedMemorySize, GS_M0);
    cudaFuncSetAttribute(mgemm_kernel<1>,
                         cudaFuncAttributeMaxDynamicSharedMemorySize, GS_M1);

    auto fw = [](const float* w1, const float* w2, int K1, int Kt, __half* out) {
        long long tot = (long long)Kt * 256;
        f16w_kernel<<<(int)((tot + 255) / 256), 256>>>(w1, w2, K1, Kt, out);
    };

    detect_kernel<<<1, 32>>>((const unsigned int*)ei);
    lam_kernel<<<(2 * HD + 255) / 256, 256>>>(a_log0, a_log1, lam);
    token_mix_kernel<<<(TV * C_IN + 255) / 256, 256>>>(xs, w_pre, b_pre, x0);
    fw(w_self0, w_neigh0, C_IN, 2 * C_IN, cat0f);
    zero_buf(agg, (long long)TV * C_IN);
    {
        long long tot = (long long)T * E * (C_IN / 4);
        scatter_kernel<<<(int)((tot + 255) / 256), 256>>>(x0, ei, agg, C_IN);
    }
    zero_buf(deg, (long long)TV);
    deg_kernel<<<(int)(((long long)T * E + 255) / 256), 256>>>(ei, deg);
    fw(w_self1, w_neigh1, H, 2 * H, cat1f);
    fw(w_res0, nullptr, C_IN, C_IN, res0f);
    fw(w_res1, nullptr, H, H, res1f);
    fw(w_mix0, nullptr, HD, HD, mix0f);
    fw(w_mix1, nullptr, HD, HD, mix1f);

    // ---------------- layer 0 ----------------
    // sage0 -> hT (transposed [hh][t][v]); res0 -> xsr
    gemm_cat(x0, agg, C_IN, deg, cat0f, b_sage0, hT, TV, 1, TV, 2 * C_IN);
    gemm_cat(x0, x0,  C_IN, nullptr, res0f, b_res0, xsr, 0, 0, TV, C_IN);

    // all 8 mix0 GEMMs, scan fused in producer (ts = z+1), fp16 1-product
    gemm_scan(hT, lam, B0, 0, mix0f, b_mix0,
              xsr, (long long)V * H, x1, (long long)V * H, V, HD, T);

    // ---------------- layer 1 ----------------
    zero_buf(agg, (long long)TV * H);
    {
        long long tot = (long long)T * E * (H / 4);
        scatter_kernel<<<(int)((tot + 255) / 256), 256>>>(x1, ei, agg, H);
    }
    gemm_cat(x1, agg, H, deg, cat1f, b_sage1, hT, TV, 1, TV, 2 * H);   // sage1 -> hT
    gemm_cat(x1 + (long long)(T - 1) * V * H, x1 + (long long)(T - 1) * V * H, H,
             nullptr, res1f, b_res1, xsrl, 0, 0, V, H);                // res1 (t=7)

    // mix1: full 8-step fused scan, single z, fp16 1-product
    gemm_scan(hT, lam + HD, B1, T, mix1f, b_mix1,
              xsrl, 0, xlast, 0, V, HD, 1);

    // ---------------- output head ----------------
    dim3 og((C_OUT + BNH - 1) / BNH, (V + BMH - 1) / BMH);
    sgemm_kernel<<<og, 256>>>(xlast, w_out, b_out, (float*)d_out, V, C_OUT, H);
}

// round 11
// speedup vs baseline: 1.6054x; 1.3089x over previous
#include <cuda_runtime.h>
#include <cuda_bf16.h>
#include <cuda_fp16.h>
#include <cstdint>

#define T 8
#define V 10000
#define E 100000
#define C_IN 128
#define H 256
#define DS 16
#define C_OUT 64
#define HD (H * DS)          // 4096
#define TV (T * V)           // 80000

// ---------------------------------------------------------------------------
// Scratch (device globals; no allocation allowed)
// ---------------------------------------------------------------------------
__device__ __align__(128) float g_x0[(size_t)TV * C_IN];
__device__ __align__(128) float g_x1[(size_t)TV * H];
__device__ __align__(128) float g_hT[(size_t)H * TV];   // sage output, [hh][t][v]
__device__ __align__(128) float g_xsr[(size_t)TV * H];
__device__ __align__(128) float g_agg[(size_t)TV * H];
__device__ __align__(128) float g_deg[(size_t)TV];
__device__ __align__(128) float g_lam[2 * HD];
__device__ __align__(128) float g_xlast[(size_t)V * H];
__device__ __align__(128) float g_xsrl [(size_t)V * H];
__device__ int g_is64;

// fp16 single-plane transposed weights ([N=256][K], K-major)
__device__ __align__(128) __half g_cat0_f[256 * 256];
__device__ __align__(128) __half g_cat1_f[256 * 512];
__device__ __align__(128) __half g_res0_f[256 * 128];
__device__ __align__(128) __half g_res1_f[256 * 256];
__device__ __align__(128) __half g_mix0_f[256 * HD];
__device__ __align__(128) __half g_mix1_f[256 * HD];

// ---------------------------------------------------------------------------
// Helpers
// ---------------------------------------------------------------------------
__device__ __forceinline__ uint32_t smem_u32(const void* p) {
    uint32_t a;
    asm("{ .reg .u64 t; cvta.to.shared.u64 t, %1; cvt.u32.u64 %0, t; }" : "=r"(a) : "l"(p));
    return a;
}

__device__ __forceinline__ uint32_t pack2h(float a, float b) {
    __half h0 = __float2half_rn(a);
    __half h1 = __float2half_rn(b);
    return (uint32_t)__half_as_ushort(h0) | ((uint32_t)__half_as_ushort(h1) << 16);
}

__device__ __forceinline__ void f16_split(float x, __half& h_, __half& l_) {
    h_ = __float2half_rn(x);
    l_ = __float2half_rn(x - __half2float(h_));
}

#define LDSM_X4(r0, r1, r2, r3, addr) \
    asm volatile("ldmatrix.sync.aligned.m8n8.x4.shared.b16 {%0,%1,%2,%3}, [%4];" \
        : "=r"(r0), "=r"(r1), "=r"(r2), "=r"(r3) : "r"(addr))

#define MMA_F16(d, a, b0, b1) \
    asm volatile("mma.sync.aligned.m16n8k16.row.col.f32.f16.f16.f32 " \
        "{%0,%1,%2,%3}, {%4,%5,%6,%7}, {%8,%9}, {%0,%1,%2,%3};" \
        : "+f"((d)[0]), "+f"((d)[1]), "+f"((d)[2]), "+f"((d)[3]) \
        : "r"((a)[0]), "r"((a)[1]), "r"((a)[2]), "r"((a)[3]), "r"(b0), "r"(b1))

#define CP16(dst, src) \
    asm volatile("cp.async.cg.shared.global [%0], [%1], 16;" :: "r"(dst), "l"(src))
#define CP_COMMIT() asm volatile("cp.async.commit_group;" ::: "memory")
#define CP_WAIT0()  asm volatile("cp.async.wait_group 0;" ::: "memory")

// ---------------------------------------------------------------------------
// Small kernels
// ---------------------------------------------------------------------------
__global__ void zero_kernel(float4* p, long long n4) {
    long long i = blockIdx.x * (long long)blockDim.x + threadIdx.x;
    long long stride = (long long)gridDim.x * blockDim.x;
    for (; i < n4; i += stride) p[i] = make_float4(0.f, 0.f, 0.f, 0.f);
}

__global__ void detect_kernel(const unsigned int* ei) {
    if (threadIdx.x == 0 && blockIdx.x == 0) {
        unsigned int s = 0;
        for (int i = 0; i < 64; i++) s |= ei[2 * i + 1];
        g_is64 = (s == 0) ? 1 : 0;
    }
}

__device__ __forceinline__ int load_edge(const void* ei, long long pos) {
    if (g_is64) return (int)((const long long*)ei)[pos];
    return ((const int*)ei)[pos];
}

__global__ void lam_kernel(const float* a0, const float* a1, float* lam) {
    int i = blockIdx.x * blockDim.x + threadIdx.x;
    if (i < HD)           lam[i] = expf(-expf(a0[i]));
    else if (i < 2 * HD)  lam[i] = expf(-expf(a1[i - HD]));
}

__global__ void token_mix_kernel(const float* __restrict__ xs,
                                 const float* __restrict__ w,
                                 const float* __restrict__ b,
                                 float* __restrict__ out) {
    int idx = blockIdx.x * blockDim.x + threadIdx.x;
    if (idx >= TV * C_IN) return;
    int c = idx % C_IN;
    int t = idx / (V * C_IN);
    float acc = b[c] + xs[idx] * w[c * 3 + 1];
    if (t > 0)     acc += xs[idx - V * C_IN] * w[c * 3 + 0];
    if (t < T - 1) acc += xs[idx + V * C_IN] * w[c * 3 + 2];
    out[idx] = acc;
}

// scatter with fused degree accumulation (c4 == 0 lane adds 1 to deg)
__global__ void scatter_kernel(const float* __restrict__ x, const void* __restrict__ ei,
                               float* __restrict__ agg, float* __restrict__ deg, int C) {
    int chunks = C >> 2;
    long long idx = blockIdx.x * (long long)blockDim.x + threadIdx.x;
    long long total = (long long)T * E * chunks;
    if (idx >= total) return;
    int c4 = (int)(idx % chunks);
    long long te = idx / chunks;
    int e = (int)(te % E);
    int t = (int)(te / E);
    long long base = (long long)t * 2 * E;
    int src = load_edge(ei, base + e);
    int dst = load_edge(ei, base + E + e);
    float4 v = *(const float4*)&x[((long long)t * V + src) * C + c4 * 4];
    float* p = &agg[((long long)t * V + dst) * C + c4 * 4];
    asm volatile("red.global.add.v4.f32 [%0], {%1,%2,%3,%4};"
                 :: "l"(p), "f"(v.x), "f"(v.y), "f"(v.z), "f"(v.w) : "memory");
    if (deg && c4 == 0) {
        float* dp = &deg[(long long)t * V + dst];
        asm volatile("red.global.add.f32 [%0], %1;" :: "l"(dp), "f"(1.0f) : "memory");
    }
}

// Build transposed fp16 weights: dst[n][k] = rn(concat(w1,w2)[k][n])
__global__ void f16w_kernel(const float* __restrict__ w1, const float* __restrict__ w2,
                            int K1, int Kt, __half* __restrict__ out) {
    long long idx = blockIdx.x * (long long)blockDim.x + threadIdx.x;
    if (idx >= (long long)Kt * 256) return;
    int k = (int)(idx % Kt);
    int n = (int)(idx / Kt);
    float v = (k < K1) ? w1[(long long)k * 256 + n] : w2[(long long)(k - K1) * 256 + n];
    out[(long long)n * Kt + k] = __float2half_rn(v);
}

// ---------------------------------------------------------------------------
// fp16 tensor GEMM, tile 64x128, BK=64, 256 threads (8 warps 2m x 4n, warp
// tile 32x32), 2 CTAs/SM, double-buffered SMEM, cp.async B (single fp16 plane).
//   MODE 0 (scan-fused, 1-product): A[r,k] = rn16(relu(Horner)); lam/Bp are
//       preloaded into SMEM once; each thread owns one hh column (16 k).
//   MODE 1 (cat, 2-product): A = concat(A1, A2*invdeg) fp32 -> fp16 hi/lo.
// C[M, n0..n0+127] = A @ B^T + bias (+ Dadd); optional transposed output.
// ---------------------------------------------------------------------------
#define ROWB 144                      // 64 k * 2B + 16 pad
#define AH_T 9216                     // 64 * 144
#define BH_T 18432                    // 128 * 144
#define STG_M0 (AH_T + BH_T)          // 27648
#define STG_M1 (2 * AH_T + BH_T)      // 36864
#define LAM_OFF (2 * STG_M0)          // 55296
#define GS_M0 (2 * STG_M0 + 32768)    // 88064 (lam 16K + Bp 16K)
#define GS_M1 (2 * STG_M1)            // 73728

template <int MODE>
__global__ __launch_bounds__(256, 2) void mgemm_kernel(
    const float* __restrict__ A1, const float* __restrict__ A2, int K1,
    const float* __restrict__ deg,
    const float* __restrict__ hT, const float* __restrict__ lam,
    const float* __restrict__ Bp, int tfix,
    const __half* __restrict__ Bf,
    const float* __restrict__ bias,
    const float* __restrict__ Dadd, long long DzS,
    float* __restrict__ Cout, long long CzS, long long CtS, int trans_out,
    int M, int K)
{
    constexpr int STG = (MODE == 0) ? STG_M0 : STG_M1;
    constexpr int B_OFF = (MODE == 0) ? AH_T : 2 * AH_T;
    extern __shared__ char smem[];
    const uint32_t sb = smem_u32(smem);
    const int tid = threadIdx.x;
    const int wid = tid >> 5;
    const int lane = tid & 31;
    const int warp_m = wid >> 2;       // 0..1
    const int warp_n = wid & 3;        // 0..3
    const int z = blockIdx.z;
    const long long m0 = (long long)blockIdx.x * 64;
    const int n0 = blockIdx.y * 128;

    const float* Dz = Dadd ? (Dadd + (long long)z * DzS) : (const float*)0;
    float* Cz = Cout + (long long)z * CzS;

    float acc[2][4][4];
#pragma unroll
    for (int i = 0; i < 2; i++)
#pragma unroll
        for (int j = 0; j < 4; j++)
#pragma unroll
            for (int p = 0; p < 4; p++) acc[i][j][p] = 0.f;

    const int nK = K / 64;
    const int ts = (MODE == 0) ? (tfix > 0 ? tfix : z + 1) : 0;

    // producer coords: q = 16-k segment (0..3), r = row (0..63)
    const int q = tid >> 6;
    const int r = tid & 63;
    const long long rg1 = m0 + r;
    const bool rowok = (rg1 < M);

    float a16[16];                     // MODE 1 staging
    float hx[8];                       // MODE 0 staging (one hh column)

    // ldmatrix base byte offsets within a stage
    const uint32_t aoff = (uint32_t)(warp_m * 32 + (lane & 15)) * ROWB +
                          (uint32_t)((lane >> 4) << 3) * 2;
    const uint32_t boff = (uint32_t)(warp_n * 32 + ((lane >> 4) << 3) + (lane & 7)) * ROWB +
                          (uint32_t)(((lane >> 3) & 1) << 3) * 2;

    // preload lam/Bp into SMEM (MODE 0): 4096 floats each
    if (MODE == 0) {
#pragma unroll
        for (int j = 0; j < 4; j++) {
            int idx = tid + 256 * j;   // 0..1023 float4s
            *(float4*)(smem + LAM_OFF + idx * 16)         = ((const float4*)lam)[idx];
            *(float4*)(smem + LAM_OFF + 16384 + idx * 16) = ((const float4*)Bp)[idx];
        }
    }

    auto cpB = [&](int kt, int stage) {
        const int k0 = kt * 64;
        const uint32_t base = sb + stage * STG + B_OFF;
#pragma unroll
        for (int i = 0; i < 4; i++) {
            int idx = tid + 256 * i;   // 0..1023
            int n  = idx >> 3;         // 0..127
            int kq = idx & 7;
            uint32_t dst = base + (uint32_t)n * ROWB + (uint32_t)kq * 16;
            long long soff = (long long)(n0 + n) * K + k0 + kq * 8;
            CP16(dst, Bf + soff);
        }
    };

    auto prefA = [&](int kt) {
        const int kg = kt * 64 + q * 16;
        if (MODE == 0) {
            const int hh = kg >> 4;    // one hh column per thread
            const long long hb = (long long)hh * TV + rg1;
#pragma unroll
            for (int tt = 0; tt < 8; tt++)
                hx[tt] = (rowok && tt < ts) ? hT[hb + (long long)tt * V] : 0.f;
        } else {
            if (rowok) {
                bool second = (kg >= K1);
                const float* src = second ? &A2[rg1 * (long long)(K - K1) + (kg - K1)]
                                          : &A1[rg1 * (long long)K1 + kg];
#pragma unroll
                for (int f = 0; f < 4; f++)
                    *(float4*)&a16[f * 4] = ((const float4*)src)[f];
                if (second && deg) {
                    float inv = 1.0f / fmaxf(deg[rg1], 1.0f);
#pragma unroll
                    for (int d = 0; d < 16; d++) a16[d] *= inv;
                }
            } else {
#pragma unroll
                for (int d = 0; d < 16; d++) a16[d] = 0.f;
            }
        }
    };

    auto produceA = [&](int stage, int kt) {
        const uint32_t off = (uint32_t)stage * STG + (uint32_t)r * ROWB + (uint32_t)q * 32;
        if (MODE == 0) {
            const int kg = kt * 64 + q * 16;
            float lam16[16], b16[16];
#pragma unroll
            for (int f = 0; f < 4; f++) {
                *(float4*)&lam16[f * 4] = *(const float4*)(smem + LAM_OFF + kg * 4 + f * 16);
                *(float4*)&b16[f * 4]   = *(const float4*)(smem + LAM_OFF + 16384 + kg * 4 + f * 16);
            }
            float s[16];
#pragma unroll
            for (int d = 0; d < 16; d++) s[d] = 0.f;
#pragma unroll
            for (int tt = 0; tt < 8; tt++) {
                if (tt < ts) {
                    float x = hx[tt];
#pragma unroll
                    for (int d = 0; d < 16; d++) s[d] = lam16[d] * s[d] + x * b16[d];
                }
            }
            uint32_t u[8];
#pragma unroll
            for (int d2 = 0; d2 < 8; d2++)
                u[d2] = pack2h(fmaxf(s[d2 * 2], 0.f), fmaxf(s[d2 * 2 + 1], 0.f));
            *(uint4*)(smem + off)      = make_uint4(u[0], u[1], u[2], u[3]);
            *(uint4*)(smem + off + 16) = make_uint4(u[4], u[5], u[6], u[7]);
        } else {
            uint32_t uh[8], ul[8];
#pragma unroll
            for (int d2 = 0; d2 < 8; d2++) {
                __half h0, l0, h1, l1;
                f16_split(a16[d2 * 2 + 0], h0, l0);
                f16_split(a16[d2 * 2 + 1], h1, l1);
                uh[d2] = (uint32_t)__half_as_ushort(h0) |
                         ((uint32_t)__half_as_ushort(h1) << 16);
                ul[d2] = (uint32_t)__half_as_ushort(l0) |
                         ((uint32_t)__half_as_ushort(l1) << 16);
            }
            *(uint4*)(smem + off)             = make_uint4(uh[0], uh[1], uh[2], uh[3]);
            *(uint4*)(smem + off + 16)        = make_uint4(uh[4], uh[5], uh[6], uh[7]);
            *(uint4*)(smem + off + AH_T)      = make_uint4(ul[0], ul[1], ul[2], ul[3]);
            *(uint4*)(smem + off + AH_T + 16) = make_uint4(ul[4], ul[5], ul[6], ul[7]);
        }
    };

    auto compute = [&](int stage) {
        const uint32_t base = sb + stage * STG;
#pragma unroll
        for (int ks = 0; ks < 4; ks++) {
            const uint32_t kk = (uint32_t)ks * 32;   // 16 k-elems = 32 bytes
            uint32_t a_h[2][4], a_l[2][4];
#pragma unroll
            for (int i = 0; i < 2; i++) {
                uint32_t ad = base + aoff + (uint32_t)(i * 16) * ROWB + kk;
                LDSM_X4(a_h[i][0], a_h[i][1], a_h[i][2], a_h[i][3], ad);
                if (MODE == 1)
                    LDSM_X4(a_l[i][0], a_l[i][1], a_l[i][2], a_l[i][3], ad + AH_T);
            }
            uint32_t b_h[8];
#pragma unroll
            for (int jj = 0; jj < 2; jj++) {
                uint32_t bd = base + B_OFF + boff + (uint32_t)(jj * 16) * ROWB + kk;
                LDSM_X4(b_h[jj * 4 + 0], b_h[jj * 4 + 1], b_h[jj * 4 + 2], b_h[jj * 4 + 3], bd);
            }
#pragma unroll
            for (int i = 0; i < 2; i++)
#pragma unroll
                for (int j = 0; j < 4; j++) {
                    MMA_F16(acc[i][j], a_h[i], b_h[j * 2], b_h[j * 2 + 1]);
                    if (MODE == 1)
                        MMA_F16(acc[i][j], a_l[i], b_h[j * 2], b_h[j * 2 + 1]);
                }
        }
    };

    // prologue
    prefA(0);
    cpB(0, 0);
    CP_COMMIT();
    if (MODE == 0) __syncthreads();    // lam/Bp smem visible
    produceA(0, 0);
    CP_WAIT0();
    __syncthreads();

    for (int kt = 0; kt < nK; kt++) {
        const int cur = kt & 1;
        const bool more = (kt + 1 < nK);
        if (more) {
            prefA(kt + 1);
            cpB(kt + 1, cur ^ 1);
            CP_COMMIT();
        }
        compute(cur);
        if (more) produceA(cur ^ 1, kt + 1);
        CP_WAIT0();
        __syncthreads();
    }

    // epilogue: warp tile 32x32 at (warp_m*32, warp_n*32)
#pragma unroll
    for (int i = 0; i < 2; i++) {
        long long r1 = m0 + warp_m * 32 + i * 16 + (lane >> 2);
        long long r2 = r1 + 8;
#pragma unroll
        for (int j = 0; j < 4; j++) {
            int c = n0 + warp_n * 32 + j * 8 + (lane & 3) * 2;
            float bx = 0.f, by = 0.f;
            if (bias) { float2 b2 = *(const float2*)&bias[c]; bx = b2.x; by = b2.y; }
            if (r1 < M) {
                float vx = acc[i][j][0] + bx, vy = acc[i][j][1] + by;
                if (Dz) { float2 d = *(const float2*)&Dz[r1 * 256 + c]; vx += d.x; vy += d.y; }
                if (trans_out) {
                    Cz[(long long)c * CtS + r1]       = vx;
                    Cz[(long long)(c + 1) * CtS + r1] = vy;
                } else {
                    *(float2*)&Cz[r1 * 256 + c] = make_float2(vx, vy);
                }
            }
            if (r2 < M) {
                float vx = acc[i][j][2] + bx, vy = acc[i][j][3] + by;
                if (Dz) { float2 d = *(const float2*)&Dz[r2 * 256 + c]; vx += d.x; vy += d.y; }
                if (trans_out) {
                    Cz[(long long)c * CtS + r2]       = vx;
                    Cz[(long long)(c + 1) * CtS + r2] = vy;
                } else {
                    *(float2*)&Cz[r2 * 256 + c] = make_float2(vx, vy);
                }
            }
        }
    }
}

// ---------------------------------------------------------------------------
// fp32 SGEMM for the small output head (N=64)
// ---------------------------------------------------------------------------
#define BMH 128
#define BNH 128
#define BKH 8

__global__ __launch_bounds__(256) void sgemm_kernel(
    const float* __restrict__ A, const float* __restrict__ B,
    const float* __restrict__ bias, float* __restrict__ C, int M, int N, int K)
{
    __shared__ float As[BKH][BMH];
    __shared__ float Bs[BKH][BNH];
    int row0 = blockIdx.y * BMH;
    int col0 = blockIdx.x * BNH;
    int tid = threadIdx.x;
    int aRow = tid >> 1;
    int aCol = (tid & 1) * 4;
    int bRow = tid >> 5;
    int bCol = (tid & 31) * 4;
    int tx = tid & 15;
    int ty = tid >> 4;
    float acc[8][8];
#pragma unroll
    for (int i = 0; i < 8; i++)
#pragma unroll
        for (int j = 0; j < 8; j++) acc[i][j] = 0.f;
    int nK = K / BKH;
    for (int kt = 0; kt < nK; ++kt) {
        int k0 = kt * BKH;
        float4 av = make_float4(0.f, 0.f, 0.f, 0.f);
        int gr = row0 + aRow;
        if (gr < M) av = *(const float4*)&A[(long long)gr * K + k0 + aCol];
        As[aCol + 0][aRow] = av.x;
        As[aCol + 1][aRow] = av.y;
        As[aCol + 2][aRow] = av.z;
        As[aCol + 3][aRow] = av.w;
        float4 bv = make_float4(0.f, 0.f, 0.f, 0.f);
        int gc = col0 + bCol;
        if (gc < N) bv = *(const float4*)&B[(long long)(k0 + bRow) * N + gc];
        *(float4*)&Bs[bRow][bCol] = bv;
        __syncthreads();
#pragma unroll
        for (int k = 0; k < BKH; k++) {
            float ar[8], br[8];
#pragma unroll
            for (int i = 0; i < 8; i++) ar[i] = As[k][ty * 8 + i];
#pragma unroll
            for (int j = 0; j < 8; j++) br[j] = Bs[k][tx * 8 + j];
#pragma unroll
            for (int i = 0; i < 8; i++)
#pragma unroll
                for (int j = 0; j < 8; j++) acc[i][j] += ar[i] * br[j];
        }
        __syncthreads();
    }
#pragma unroll
    for (int i = 0; i < 8; i++) {
        int r = row0 + ty * 8 + i;
        if (r >= M) continue;
#pragma unroll
        for (int j = 0; j < 8; j++) {
            int c = col0 + tx * 8 + j;
            if (c >= N) continue;
            C[(long long)r * N + c] = acc[i][j] + bias[c];
        }
    }
}

// ---------------------------------------------------------------------------
// Host helpers
// ---------------------------------------------------------------------------
static void zero_buf(float* p, long long n_floats) {
    zero_kernel<<<1024, 256>>>((float4*)p, n_floats / 4);
}

static void gemm_cat(const float* A1, const float* A2, int K1, const float* deg,
                     const __half* Bf,
                     const float* bias, float* C, long long CtS, int trans,
                     int M, int K) {
    dim3 grid((M + 63) / 64, 2, 1);
    mgemm_kernel<1><<<grid, 256, GS_M1>>>(A1, A2, K1, deg,
                                          nullptr, nullptr, nullptr, 0,
                                          Bf, bias, nullptr, 0,
                                          C, 0, CtS, trans, M, K);
}

static void gemm_scan(const float* hT, const float* lam, const float* Bp, int tfix,
                      const __half* Bf,
                      const float* bias, const float* Dadd, long long DzS,
                      float* C, long long CzS, int M, int K, int nz) {
    dim3 grid((M + 63) / 64, 2, nz);
    mgemm_kernel<0><<<grid, 256, GS_M0>>>(nullptr, nullptr, 0, nullptr,
                                          hT, lam, Bp, tfix,
                                          Bf, bias, Dadd, DzS,
                                          C, CzS, 0, 0, M, K);
}

// ---------------------------------------------------------------------------
// Launch
// ---------------------------------------------------------------------------
extern "C" void kernel_launch(void* const* d_in, const int* in_sizes, int n_in,
                              void* d_out, int out_size) {
    const float* xs      = (const float*)d_in[0];
    const void*  ei      = d_in[1];
    const float* w_pre   = (const float*)d_in[2];
    const float* b_pre   = (const float*)d_in[3];

    const float* w_res0  = (const float*)d_in[4];
    const float* b_res0  = (const float*)d_in[5];
    const float* w_self0 = (const float*)d_in[6];
    const float* w_neigh0= (const float*)d_in[7];
    const float* b_sage0 = (const float*)d_in[8];
    const float* a_log0  = (const float*)d_in[9];
    const float* B0      = (const float*)d_in[10];
    const float* w_mix0  = (const float*)d_in[11];
    const float* b_mix0  = (const float*)d_in[12];

    const float* w_res1  = (const float*)d_in[13];
    const float* b_res1  = (const float*)d_in[14];
    const float* w_self1 = (const float*)d_in[15];
    const float* w_neigh1= (const float*)d_in[16];
    const float* b_sage1 = (const float*)d_in[17];
    const float* a_log1  = (const float*)d_in[18];
    const float* B1      = (const float*)d_in[19];
    const float* w_mix1  = (const float*)d_in[20];
    const float* b_mix1  = (const float*)d_in[21];

    const float* w_out   = (const float*)d_in[22];
    const float* b_out   = (const float*)d_in[23];

    float *x0, *x1, *hT, *xsr, *agg, *deg, *lam, *xlast, *xsrl;
    cudaGetSymbolAddress((void**)&x0,    g_x0);
    cudaGetSymbolAddress((void**)&x1,    g_x1);
    cudaGetSymbolAddress((void**)&hT,    g_hT);
    cudaGetSymbolAddress((void**)&xsr,   g_xsr);
    cudaGetSymbolAddress((void**)&agg,   g_agg);
    cudaGetSymbolAddress((void**)&deg,   g_deg);
    cudaGetSymbolAddress((void**)&lam,   g_lam);
    cudaGetSymbolAddress((void**)&xlast, g_xlast);
    cudaGetSymbolAddress((void**)&xsrl,  g_xsrl);

    __half *cat0f, *cat1f, *res0f, *res1f, *mix0f, *mix1f;
    cudaGetSymbolAddress((void**)&cat0f, g_cat0_f);
    cudaGetSymbolAddress((void**)&cat1f, g_cat1_f);
    cudaGetSymbolAddress((void**)&res0f, g_res0_f);
    cudaGetSymbolAddress((void**)&res1f, g_res1_f);
    cudaGetSymbolAddress((void**)&mix0f, g_mix0_f);
    cudaGetSymbolAddress((void**)&mix1f, g_mix1_f);

    cudaFuncSetAttribute(mgemm_kernel<0>,
                         cudaFuncAttributeMaxDynamicSharedMemorySize, GS_M0);
    cudaFuncSetAttribute(mgemm_kernel<1>,
                         cudaFuncAttributeMaxDynamicSharedMemorySize, GS_M1);

    auto fw = [](const float* w1, const float* w2, int K1, int Kt, __half* out) {
        long long tot = (long long)Kt * 256;
        f16w_kernel<<<(int)((tot + 255) / 256), 256>>>(w1, w2, K1, Kt, out);
    };

    detect_kernel<<<1, 32>>>((const unsigned int*)ei);
    lam_kernel<<<(2 * HD + 255) / 256, 256>>>(a_log0, a_log1, lam);
    token_mix_kernel<<<(TV * C_IN + 255) / 256, 256>>>(xs, w_pre, b_pre, x0);
    fw(w_self0, w_neigh0, C_IN, 2 * C_IN, cat0f);
    zero_buf(agg, (long long)TV * C_IN);
    zero_buf(deg, (long long)TV);
    {
        long long tot = (long long)T * E * (C_IN / 4);
        scatter_kernel<<<(int)((tot + 255) / 256), 256>>>(x0, ei, agg, deg, C_IN);
    }
    fw(w_self1, w_neigh1, H, 2 * H, cat1f);
    fw(w_res0, nullptr, C_IN, C_IN, res0f);
    fw(w_res1, nullptr, H, H, res1f);
    fw(w_mix0, nullptr, HD, HD, mix0f);
    fw(w_mix1, nullptr, HD, HD, mix1f);

    // ---------------- layer 0 ----------------
    // sage0 -> hT (transposed [hh][t][v]); res0 -> xsr
    gemm_cat(x0, agg, C_IN, deg, cat0f, b_sage0, hT, TV, 1, TV, 2 * C_IN);
    gemm_cat(x0, x0,  C_IN, nullptr, res0f, b_res0, xsr, 0, 0, TV, C_IN);

    // all 8 mix0 GEMMs, scan fused in producer (ts = z+1), fp16 1-product
    gemm_scan(hT, lam, B0, 0, mix0f, b_mix0,
              xsr, (long long)V * H, x1, (long long)V * H, V, HD, T);

    // ---------------- layer 1 ----------------
    zero_buf(agg, (long long)TV * H);
    {
        long long tot = (long long)T * E * (H / 4);
        scatter_kernel<<<(int)((tot + 255) / 256), 256>>>(x1, ei, agg, nullptr, H);
    }
    gemm_cat(x1, agg, H, deg, cat1f, b_sage1, hT, TV, 1, TV, 2 * H);   // sage1 -> hT
    gemm_cat(x1 + (long long)(T - 1) * V * H, x1 + (long long)(T - 1) * V * H, H,
             nullptr, res1f, b_res1, xsrl, 0, 0, V, H);                // res1 (t=7)

    // mix1: full 8-step fused scan, single z, fp16 1-product
    gemm_scan(hT, lam + HD, B1, T, mix1f, b_mix1,
              xsrl, 0, xlast, 0, V, HD, 1);

    // ---------------- output head ----------------
    dim3 og((C_OUT + BNH - 1) / BNH, (V + BMH - 1) / BMH);
    sgemm_kernel<<<og, 256>>>(xlast, w_out, b_out, (float*)d_out, V, C_OUT, H);
}